// round 12
// baseline (speedup 1.0000x reference)
#include <cuda_runtime.h>
#include <cuda_bf16.h>
#include <math_constants.h>
#include <cstdint>

#define T_DIM 2048
#define B_DIM 2
#define E_DIM 1024
#define H_DIM 16
#define D_DIM 64
#define NHEADS 32
#define NROWS  4096

// Scratch (device globals; no runtime allocation)
__device__ float         g_Qtf[NROWS * E_DIM];   // tf32, scale*log2e folded
__device__ float         g_Ktf[NROWS * E_DIM];   // tf32
__device__ __nv_bfloat16 g_Vhb[NROWS * E_DIM], g_Vlb[NROWS * E_DIM];
__device__ float         g_ctx[NROWS * E_DIM];   // tf32-rounded
__device__ float         g_q[NROWS * E_DIM], g_k[NROWS * E_DIM], g_v[NROWS * E_DIM];
__device__ float         g_Win[3 * E_DIM * E_DIM], g_Wout[E_DIM * E_DIM];

// ---------------- helpers ----------------
__device__ __forceinline__ void ldsm4(uint32_t* r, uint32_t a) {
    asm volatile("ldmatrix.sync.aligned.m8n8.x4.shared.b16 {%0,%1,%2,%3}, [%4];"
                 : "=r"(r[0]), "=r"(r[1]), "=r"(r[2]), "=r"(r[3]) : "r"(a));
}
__device__ __forceinline__ void ldsm4t(uint32_t* r, uint32_t a) {
    asm volatile("ldmatrix.sync.aligned.m8n8.x4.trans.shared.b16 {%0,%1,%2,%3}, [%4];"
                 : "=r"(r[0]), "=r"(r[1]), "=r"(r[2]), "=r"(r[3]) : "r"(a));
}
__device__ __forceinline__ void mma_bf16(float* d, const uint32_t* a, uint32_t b0, uint32_t b1) {
    asm volatile("mma.sync.aligned.m16n8k16.row.col.f32.bf16.bf16.f32 "
                 "{%0,%1,%2,%3}, {%4,%5,%6,%7}, {%8,%9}, {%0,%1,%2,%3};"
                 : "+f"(d[0]), "+f"(d[1]), "+f"(d[2]), "+f"(d[3])
                 : "r"(a[0]), "r"(a[1]), "r"(a[2]), "r"(a[3]), "r"(b0), "r"(b1));
}
__device__ __forceinline__ void mma_tf32(float* d, const uint32_t* a, uint32_t b0, uint32_t b1) {
    asm volatile("mma.sync.aligned.m16n8k8.row.col.f32.tf32.tf32.f32 "
                 "{%0,%1,%2,%3}, {%4,%5,%6,%7}, {%8,%9}, {%0,%1,%2,%3};"
                 : "+f"(d[0]), "+f"(d[1]), "+f"(d[2]), "+f"(d[3])
                 : "r"(a[0]), "r"(a[1]), "r"(a[2]), "r"(a[3]), "r"(b0), "r"(b1));
}
__device__ __forceinline__ uint32_t smem_u32(const void* p) {
    return (uint32_t)__cvta_generic_to_shared(p);
}
__device__ __forceinline__ void cp_async16(uint32_t d, const void* s) {
    asm volatile("cp.async.cg.shared.global [%0], [%1], 16;" :: "r"(d), "l"(s));
}
__device__ __forceinline__ void cp_commit() { asm volatile("cp.async.commit_group;"); }
template <int N> __device__ __forceinline__ void cp_wait() {
    asm volatile("cp.async.wait_group %0;" :: "n"(N));
}
__device__ __forceinline__ uint32_t pack_bf16(__nv_bfloat16 x, __nv_bfloat16 y) {
    __nv_bfloat162 v = __halves2bfloat162(x, y);
    return *reinterpret_cast<uint32_t*>(&v);
}
__device__ __forceinline__ void split2(float a, float b, uint32_t& hi, uint32_t& lo) {
    __nv_bfloat16 ha = __float2bfloat16(a), hb = __float2bfloat16(b);
    hi = pack_bf16(ha, hb);
    lo = pack_bf16(__float2bfloat16(a - __bfloat162float(ha)),
                   __float2bfloat16(b - __bfloat162float(hb)));
}
__device__ __forceinline__ float to_tf32(float x) {
    uint32_t r; asm("cvt.rna.tf32.f32 %0, %1;" : "=r"(r) : "f"(x));
    return __uint_as_float(r);
}
__device__ __forceinline__ float ex2f(float x) {
    float y; asm("ex2.approx.ftz.f32 %0, %1;" : "=f"(y) : "f"(x));
    return y;
}

// ---------------- merged tf32-RNA preround (segment ladder, one launch) ----------------
__global__ __launch_bounds__(256) void preround_all(const float* __restrict__ q,
    const float* __restrict__ k, const float* __restrict__ v,
    const float* __restrict__ Win, const float* __restrict__ Wout)
{
    const long i = (long)blockIdx.x * 256 + threadIdx.x;
    const float* src; float* dst; long off;
    if (i < 1048576)      { src = q;    dst = g_q;    off = i; }
    else if (i < 2097152) { src = k;    dst = g_k;    off = i - 1048576; }
    else if (i < 3145728) { src = v;    dst = g_v;    off = i - 2097152; }
    else if (i < 3932160) { src = Win;  dst = g_Win;  off = i - 3145728; }
    else                  { src = Wout; dst = g_Wout; off = i - 3932160; }
    float4 x = ((const float4*)src)[off];
    ((float4*)dst)[off] = make_float4(to_tf32(x.x), to_tf32(x.y),
                                      to_tf32(x.z), to_tf32(x.w));
}

// ---------------- tf32 GEMM, 3-stage cp.async (unchanged, known-good) ----------------
#define GT 18432
#define GSTAGE (2 * GT)
#define GSMEM (3 * GSTAGE)

__global__ __launch_bounds__(256, 2) void gemm_tf32(const float* __restrict__ A0,
    const float* __restrict__ A1, const float* __restrict__ A2,
    const float* __restrict__ W,  const float* __restrict__ bias,
    float* __restrict__ Qtf, float* __restrict__ Ktf,
    __nv_bfloat16* __restrict__ Vhb, __nv_bfloat16* __restrict__ Vlb,
    float* __restrict__ Cflat, float scaleQ, int qkv)
{
    extern __shared__ __align__(16) char gsm[];
    const int z = qkv ? blockIdx.z : 0;
    const float* A  = qkv ? (z == 0 ? A0 : (z == 1 ? A1 : A2)) : A0;
    const float* Wz = W + (size_t)z * E_DIM * E_DIM;
    const float* bz = bias + z * E_DIM;
    const int   mode  = qkv ? (z == 2 ? 1 : 2) : 0;
    const float scale = (qkv && z == 0) ? scaleQ : 1.f;
    float* Cf = (z == 0) ? Qtf : Ktf;

    const int tid = threadIdx.x, lane = tid & 31, wid = tid >> 5;
    const int wm = wid >> 2, wn = wid & 3;
    const int bm = blockIdx.y << 7, bn = blockIdx.x << 7;
    const int lrow = lane & 15, lk16 = ((lane >> 4) & 1) << 4;
    const uint32_t uS = smem_u32(gsm);

    float acc[4][4][4];
    #pragma unroll
    for (int i = 0; i < 4; i++)
        #pragma unroll
        for (int j = 0; j < 4; j++)
            #pragma unroll
            for (int r = 0; r < 4; r++) acc[i][j][r] = 0.f;

    const int crow0 = tid >> 3;
    const int cjf   = (tid & 7) << 2;
    const float* gA = A  + (size_t)bm * E_DIM;
    const float* gW = Wz + (size_t)bn * E_DIM;

    #pragma unroll
    for (int s = 0; s < 2; s++) {
        const uint32_t dst = uS + (uint32_t)s * GSTAGE;
        const int kc = s * 32;
        #pragma unroll
        for (int it = 0; it < 4; it++) {
            const int row = crow0 + it * 32;
            const uint32_t off = (uint32_t)row * 144 + (uint32_t)cjf * 4;
            cp_async16(dst + off,      gA + (size_t)row * E_DIM + kc + cjf);
            cp_async16(dst + GT + off, gW + (size_t)row * E_DIM + kc + cjf);
        }
        cp_commit();
    }

    const int NK = E_DIM / 32;
    for (int kt = 0; kt < NK; kt++) {
        cp_wait<1>();
        __syncthreads();
        if (kt + 2 < NK) {
            const uint32_t dst = uS + (uint32_t)((kt + 2) % 3) * GSTAGE;
            const int kc = (kt + 2) * 32;
            #pragma unroll
            for (int it = 0; it < 4; it++) {
                const int row = crow0 + it * 32;
                const uint32_t off = (uint32_t)row * 144 + (uint32_t)cjf * 4;
                cp_async16(dst + off,      gA + (size_t)row * E_DIM + kc + cjf);
                cp_async16(dst + GT + off, gW + (size_t)row * E_DIM + kc + cjf);
            }
        }
        cp_commit();

        const uint32_t pA = uS + (uint32_t)(kt % 3) * GSTAGE;
        const uint32_t pW = pA + GT;
        #pragma unroll
        for (int kk = 0; kk < 4; kk++) {
            uint32_t Af[4][4];
            #pragma unroll
            for (int mt = 0; mt < 4; mt++)
                ldsm4(Af[mt], pA + (uint32_t)(wm * 64 + mt * 16 + lrow) * 144 + kk * 32 + lk16);
            uint32_t Bf[2][4];
            #pragma unroll
            for (int nb = 0; nb < 2; nb++)
                ldsm4(Bf[nb], pW + (uint32_t)(wn * 32 + nb * 16 + lrow) * 144 + kk * 32 + lk16);
            #pragma unroll
            for (int mt = 0; mt < 4; mt++) {
                #pragma unroll
                for (int nt = 0; nt < 4; nt++) {
                    const int nb = nt >> 1, hf = nt & 1;
                    mma_tf32(acc[mt][nt], Af[mt], Bf[nb][hf], Bf[nb][hf + 2]);
                }
            }
        }
    }

    const int g = lane >> 2, tig = lane & 3;
    #pragma unroll
    for (int mt = 0; mt < 4; mt++) {
        #pragma unroll
        for (int nt = 0; nt < 4; nt++) {
            const int m0 = bm + wm * 64 + mt * 16 + g;
            const int n0 = bn + wn * 32 + nt * 8 + tig * 2;
            const float b0 = bz[n0], b1 = bz[n0 + 1];
            float v[4];
            #pragma unroll
            for (int r = 0; r < 4; r++)
                v[r] = (acc[mt][nt][r] + ((r & 1) ? b1 : b0)) * scale;
            if (mode == 1) {
                #pragma unroll
                for (int rr = 0; rr < 2; rr++) {
                    const int m = m0 + rr * 8;
                    const int t = m >> 1, b = m & 1, h = n0 >> 6, dd = n0 & 63;
                    uint32_t hi, lo;
                    split2(v[rr * 2], v[rr * 2 + 1], hi, lo);
                    const size_t idx = (((size_t)(b * H_DIM + h)) * T_DIM + t) * D_DIM + dd;
                    *reinterpret_cast<uint32_t*>(&Vhb[idx]) = hi;
                    *reinterpret_cast<uint32_t*>(&Vlb[idx]) = lo;
                }
            } else if (mode == 2) {
                #pragma unroll
                for (int rr = 0; rr < 2; rr++) {
                    const int m = m0 + rr * 8;
                    const int t = m >> 1, b = m & 1, h = n0 >> 6, dd = n0 & 63;
                    const size_t idx = (((size_t)(b * H_DIM + h)) * T_DIM + t) * D_DIM + dd;
                    *(float2*)(Cf + idx) = make_float2(to_tf32(v[rr * 2]),
                                                       to_tf32(v[rr * 2 + 1]));
                }
            } else {
                #pragma unroll
                for (int r = 0; r < 4; r++) {
                    const int m = m0 + ((r >> 1) << 3);
                    const int n = n0 + (r & 1);
                    Cflat[(size_t)m * E_DIM + n] = v[r];
                }
            }
        }
    }
}

// ---------------- flash attention: 128q tile, 8 warps, K double-buf + V single-buf ----------------
#define AQ   0
#define AK0  34816
#define AK1  52224
#define AVH  69632
#define AVL  78848
#define ATT_SMEM 88064

__global__ __launch_bounds__(256, 2) void attn_mma(
    const float* __restrict__ Qtf, const float* __restrict__ Ktf,
    const __nv_bfloat16* __restrict__ Vhb, const __nv_bfloat16* __restrict__ Vlb,
    float* __restrict__ ctx)
{
    extern __shared__ __align__(16) char smraw[];
    const int tid = threadIdx.x, lane = tid & 31, w = tid >> 5;   // w: 0..7
    const int qt = blockIdx.x, hg = blockIdx.y;
    const int lrow = lane & 15, lk16 = ((lane >> 4) & 1) << 4;
    const int rg = lane >> 2, tig = lane & 3;
    const uint32_t uSM = smem_u32(smraw);

    const float* gK = Ktf + (size_t)hg * T_DIM * D_DIM;
    const __nv_bfloat16* gVh = Vhb + (size_t)hg * T_DIM * D_DIM;
    const __nv_bfloat16* gVl = Vlb + (size_t)hg * T_DIM * D_DIM;

    // group 1: Q (128 rows x 64 tf32 = 2048 16B chunks)
    {
        const float* gq = Qtf + ((size_t)hg * T_DIM + qt * 128) * D_DIM;
        #pragma unroll
        for (int i = 0; i < 8; i++) {
            int c = tid + i * 256, row = c >> 4, j = c & 15;
            cp_async16(uSM + AQ + row * 272 + j * 16, gq + c * 4);
        }
        cp_commit();
    }
    // group 2: K tile 0 -> buf0 (1024 chunks)
    {
        #pragma unroll
        for (int i = 0; i < 4; i++) {
            int c = tid + i * 256, row = c >> 4, j = c & 15;
            cp_async16(uSM + AK0 + row * 272 + j * 16, gK + c * 4);
        }
        cp_commit();
    }

    float o[8][4];
    #pragma unroll
    for (int nt = 0; nt < 8; nt++)
        #pragma unroll
        for (int r = 0; r < 4; r++) o[nt][r] = 0.f;
    float m0 = -CUDART_INF_F, m1 = -CUDART_INF_F, l0 = 0.f, l1 = 0.f;

    for (int st = 0; st < T_DIM / 64; st++) {
        __syncthreads();          // V buffer + old K buffer reads done
        // issue V(st): 512 chunks each
        #pragma unroll
        for (int i = 0; i < 2; i++) {
            int c = tid + i * 256, row = c >> 3, j = c & 7;
            int off = row * 144 + j * 16;
            cp_async16(uSM + AVH + off, gVh + (size_t)st * 4096 + c * 8);
            cp_async16(uSM + AVL + off, gVl + (size_t)st * 4096 + c * 8);
        }
        cp_commit();
        // issue K(st+1) into other buffer; then ensure K(st) resident
        if (st + 1 < T_DIM / 64) {
            const uint32_t kb = uSM + (((st + 1) & 1) ? AK1 : AK0);
            #pragma unroll
            for (int i = 0; i < 4; i++) {
                int c = tid + i * 256, row = c >> 4, j = c & 15;
                cp_async16(kb + row * 272 + j * 16, gK + (size_t)(st + 1) * 4096 + c * 4);
            }
            cp_commit();
            cp_wait<2>();         // K(st) (+Q at st=0) arrived
        } else {
            cp_wait<1>();
        }
        __syncthreads();

        // ---- S = Q K^T (tf32) on K buffer st&1 ----
        const uint32_t kbuf = uSM + ((st & 1) ? AK1 : AK0);
        float s[8][4];
        #pragma unroll
        for (int nt = 0; nt < 8; nt++)
            #pragma unroll
            for (int r = 0; r < 4; r++) s[nt][r] = 0.f;
        #pragma unroll
        for (int kk = 0; kk < 8; kk++) {
            uint32_t qa[4];
            ldsm4(qa, uSM + AQ + (uint32_t)(w * 16 + lrow) * 272 + kk * 32 + lk16);
            uint32_t kf[4][4];
            #pragma unroll
            for (int nb = 0; nb < 4; nb++)
                ldsm4(kf[nb], kbuf + (uint32_t)(nb * 16 + lrow) * 272 + kk * 32 + lk16);
            #pragma unroll
            for (int nb = 0; nb < 4; nb++) {
                mma_tf32(s[2 * nb],     qa, kf[nb][0], kf[nb][2]);
                mma_tf32(s[2 * nb + 1], qa, kf[nb][1], kf[nb][3]);
            }
        }

        // ---- online softmax (exp2 domain) ----
        float mx0 = -CUDART_INF_F, mx1 = -CUDART_INF_F;
        #pragma unroll
        for (int nt = 0; nt < 8; nt++) {
            mx0 = fmaxf(mx0, fmaxf(s[nt][0], s[nt][1]));
            mx1 = fmaxf(mx1, fmaxf(s[nt][2], s[nt][3]));
        }
        mx0 = fmaxf(mx0, __shfl_xor_sync(~0u, mx0, 1));
        mx0 = fmaxf(mx0, __shfl_xor_sync(~0u, mx0, 2));
        mx1 = fmaxf(mx1, __shfl_xor_sync(~0u, mx1, 1));
        mx1 = fmaxf(mx1, __shfl_xor_sync(~0u, mx1, 2));
        const float mn0 = fmaxf(m0, mx0), mn1 = fmaxf(m1, mx1);
        const float al0 = ex2f(m0 - mn0), al1 = ex2f(m1 - mn1);
        m0 = mn0; m1 = mn1;
        float sum0 = 0.f, sum1 = 0.f;
        #pragma unroll
        for (int nt = 0; nt < 8; nt++) {
            s[nt][0] = ex2f(s[nt][0] - m0); s[nt][1] = ex2f(s[nt][1] - m0);
            s[nt][2] = ex2f(s[nt][2] - m1); s[nt][3] = ex2f(s[nt][3] - m1);
            sum0 += s[nt][0] + s[nt][1];
            sum1 += s[nt][2] + s[nt][3];
        }
        sum0 += __shfl_xor_sync(~0u, sum0, 1); sum0 += __shfl_xor_sync(~0u, sum0, 2);
        sum1 += __shfl_xor_sync(~0u, sum1, 1); sum1 += __shfl_xor_sync(~0u, sum1, 2);
        l0 = l0 * al0 + sum0; l1 = l1 * al1 + sum1;
        #pragma unroll
        for (int nt = 0; nt < 8; nt++) {
            o[nt][0] *= al0; o[nt][1] *= al0; o[nt][2] *= al1; o[nt][3] *= al1;
        }

        // ---- P -> bf16 hi/lo fragments ----
        uint32_t AH[4][4], AL[4][4];
        #pragma unroll
        for (int kb = 0; kb < 4; kb++) {
            const int t0 = 2 * kb, t1 = 2 * kb + 1;
            split2(s[t0][0], s[t0][1], AH[kb][0], AL[kb][0]);
            split2(s[t0][2], s[t0][3], AH[kb][1], AL[kb][1]);
            split2(s[t1][0], s[t1][1], AH[kb][2], AL[kb][2]);
            split2(s[t1][2], s[t1][3], AH[kb][3], AL[kb][3]);
        }

        // ---- wait V(st), then O += P V (bf16x3) ----
        if (st + 1 < T_DIM / 64) cp_wait<1>(); else cp_wait<0>();
        __syncthreads();
        #pragma unroll
        for (int kb = 0; kb < 4; kb++) {
            uint32_t vh[4][4], vl[4][4];
            #pragma unroll
            for (int db = 0; db < 4; db++) {
                const uint32_t a = uSM + AVH + (uint32_t)(kb * 16 + lrow) * 144 + db * 32 + lk16;
                ldsm4t(vh[db], a);
                ldsm4t(vl[db], a + (AVL - AVH));
            }
            #pragma unroll
            for (int db = 0; db < 4; db++) {
                #pragma unroll
                for (int hs = 0; hs < 2; hs++) {
                    const int nt = db * 2 + hs;
                    mma_bf16(o[nt], AH[kb], vh[db][hs * 2], vh[db][hs * 2 + 1]);
                    mma_bf16(o[nt], AL[kb], vh[db][hs * 2], vh[db][hs * 2 + 1]);
                    mma_bf16(o[nt], AH[kb], vl[db][hs * 2], vl[db][hs * 2 + 1]);
                }
            }
        }
    }

    // ---- epilogue: tf32-rounded ctx ----
    const float inv0 = 1.f / l0, inv1 = 1.f / l1;
    const int bb = hg >> 4, hh = hg & 15;
    const int q0 = qt * 128 + w * 16 + rg;
    #pragma unroll
    for (int nt = 0; nt < 8; nt++) {
        const int d = hh * 64 + nt * 8 + tig * 2;
        *(float2*)(ctx + ((size_t)q0 * B_DIM + bb) * E_DIM + d) =
            make_float2(to_tf32(o[nt][0] * inv0), to_tf32(o[nt][1] * inv0));
        *(float2*)(ctx + ((size_t)(q0 + 8) * B_DIM + bb) * E_DIM + d) =
            make_float2(to_tf32(o[nt][2] * inv1), to_tf32(o[nt][3] * inv1));
    }
}

// ---------------------------------------------------------------------------
extern "C" void kernel_launch(void* const* d_in, const int* in_sizes, int n_in,
                              void* d_out, int out_size)
{
    const float* query = (const float*)d_in[0];
    const float* key   = (const float*)d_in[1];
    const float* value = (const float*)d_in[2];
    const float* Win   = (const float*)d_in[3];
    const float* bin   = (const float*)d_in[4];
    const float* Wout  = (const float*)d_in[5];
    const float* bout  = (const float*)d_in[6];
    float* out = (float*)d_out;

    float *Qtf, *Ktf, *ctx, *q_r, *k_r, *v_r, *Win_r, *Wout_r;
    __nv_bfloat16 *Vhb, *Vlb;
    cudaGetSymbolAddress((void**)&Qtf,    g_Qtf);
    cudaGetSymbolAddress((void**)&Ktf,    g_Ktf);
    cudaGetSymbolAddress((void**)&Vhb,    g_Vhb);
    cudaGetSymbolAddress((void**)&Vlb,    g_Vlb);
    cudaGetSymbolAddress((void**)&ctx,    g_ctx);
    cudaGetSymbolAddress((void**)&q_r,    g_q);
    cudaGetSymbolAddress((void**)&k_r,    g_k);
    cudaGetSymbolAddress((void**)&v_r,    g_v);
    cudaGetSymbolAddress((void**)&Win_r,  g_Win);
    cudaGetSymbolAddress((void**)&Wout_r, g_Wout);

    const float scaleQ = 0.125f * 1.44269504089f;   // 1/sqrt(64) * log2(e)

    cudaFuncSetAttribute(gemm_tf32, cudaFuncAttributeMaxDynamicSharedMemorySize, GSMEM);
    cudaFuncSetAttribute(attn_mma,  cudaFuncAttributeMaxDynamicSharedMemorySize, ATT_SMEM);

    preround_all<<<16384, 256>>>(query, key, value, Win, Wout);

    gemm_tf32<<<dim3(8, 32, 3), 256, GSMEM>>>(
        q_r, k_r, v_r, Win_r, bin, Qtf, Ktf, Vhb, Vlb, nullptr, scaleQ, 1);

    attn_mma<<<dim3(16, 32), 256, ATT_SMEM>>>(Qtf, Ktf, Vhb, Vlb, ctx);

    gemm_tf32<<<dim3(8, 32, 1), 256, GSMEM>>>(
        ctx, nullptr, nullptr, Wout_r, bout, nullptr, nullptr, nullptr, nullptr, out, 1.f, 0);
}

// round 13
// speedup vs baseline: 1.0476x; 1.0476x over previous
#include <cuda_runtime.h>
#include <cuda_bf16.h>
#include <math_constants.h>
#include <cstdint>

#define T_DIM 2048
#define B_DIM 2
#define E_DIM 1024
#define H_DIM 16
#define D_DIM 64
#define NHEADS 32
#define NROWS  4096

// Scratch (device globals; no runtime allocation)
__device__ float         g_Qtf[NROWS * E_DIM];   // tf32, scale*log2e folded
__device__ float         g_Ktf[NROWS * E_DIM];   // tf32
__device__ __nv_bfloat16 g_Vhb[NROWS * E_DIM], g_Vlb[NROWS * E_DIM];
__device__ float         g_ctx[NROWS * E_DIM];   // tf32-rounded
__device__ float         g_q[NROWS * E_DIM], g_k[NROWS * E_DIM], g_v[NROWS * E_DIM];
__device__ float         g_Win[3 * E_DIM * E_DIM], g_Wout[E_DIM * E_DIM];

// ---------------- helpers ----------------
__device__ __forceinline__ void ldsm4(uint32_t* r, uint32_t a) {
    asm volatile("ldmatrix.sync.aligned.m8n8.x4.shared.b16 {%0,%1,%2,%3}, [%4];"
                 : "=r"(r[0]), "=r"(r[1]), "=r"(r[2]), "=r"(r[3]) : "r"(a));
}
__device__ __forceinline__ void ldsm4t(uint32_t* r, uint32_t a) {
    asm volatile("ldmatrix.sync.aligned.m8n8.x4.trans.shared.b16 {%0,%1,%2,%3}, [%4];"
                 : "=r"(r[0]), "=r"(r[1]), "=r"(r[2]), "=r"(r[3]) : "r"(a));
}
__device__ __forceinline__ void mma_bf16(float* d, const uint32_t* a, uint32_t b0, uint32_t b1) {
    asm volatile("mma.sync.aligned.m16n8k16.row.col.f32.bf16.bf16.f32 "
                 "{%0,%1,%2,%3}, {%4,%5,%6,%7}, {%8,%9}, {%0,%1,%2,%3};"
                 : "+f"(d[0]), "+f"(d[1]), "+f"(d[2]), "+f"(d[3])
                 : "r"(a[0]), "r"(a[1]), "r"(a[2]), "r"(a[3]), "r"(b0), "r"(b1));
}
__device__ __forceinline__ void mma_tf32(float* d, const uint32_t* a, uint32_t b0, uint32_t b1) {
    asm volatile("mma.sync.aligned.m16n8k8.row.col.f32.tf32.tf32.f32 "
                 "{%0,%1,%2,%3}, {%4,%5,%6,%7}, {%8,%9}, {%0,%1,%2,%3};"
                 : "+f"(d[0]), "+f"(d[1]), "+f"(d[2]), "+f"(d[3])
                 : "r"(a[0]), "r"(a[1]), "r"(a[2]), "r"(a[3]), "r"(b0), "r"(b1));
}
__device__ __forceinline__ uint32_t smem_u32(const void* p) {
    return (uint32_t)__cvta_generic_to_shared(p);
}
__device__ __forceinline__ void cp_async16(uint32_t d, const void* s) {
    asm volatile("cp.async.cg.shared.global [%0], [%1], 16;" :: "r"(d), "l"(s));
}
__device__ __forceinline__ void cp_commit() { asm volatile("cp.async.commit_group;"); }
template <int N> __device__ __forceinline__ void cp_wait() {
    asm volatile("cp.async.wait_group %0;" :: "n"(N));
}
__device__ __forceinline__ uint32_t pack_bf16(__nv_bfloat16 x, __nv_bfloat16 y) {
    __nv_bfloat162 v = __halves2bfloat162(x, y);
    return *reinterpret_cast<uint32_t*>(&v);
}
__device__ __forceinline__ void split2(float a, float b, uint32_t& hi, uint32_t& lo) {
    __nv_bfloat16 ha = __float2bfloat16(a), hb = __float2bfloat16(b);
    hi = pack_bf16(ha, hb);
    lo = pack_bf16(__float2bfloat16(a - __bfloat162float(ha)),
                   __float2bfloat16(b - __bfloat162float(hb)));
}
__device__ __forceinline__ float to_tf32(float x) {
    uint32_t r; asm("cvt.rna.tf32.f32 %0, %1;" : "=r"(r) : "f"(x));
    return __uint_as_float(r);
}
__device__ __forceinline__ float ex2f(float x) {
    float y; asm("ex2.approx.ftz.f32 %0, %1;" : "=f"(y) : "f"(x));
    return y;
}

// ---------------- merged tf32-RNA preround (segment ladder, one launch) ----------------
__global__ __launch_bounds__(256) void preround_all(const float* __restrict__ q,
    const float* __restrict__ k, const float* __restrict__ v,
    const float* __restrict__ Win, const float* __restrict__ Wout)
{
    const long i = (long)blockIdx.x * 256 + threadIdx.x;
    const float* src; float* dst; long off;
    if (i < 1048576)      { src = q;    dst = g_q;    off = i; }
    else if (i < 2097152) { src = k;    dst = g_k;    off = i - 1048576; }
    else if (i < 3145728) { src = v;    dst = g_v;    off = i - 2097152; }
    else if (i < 3932160) { src = Win;  dst = g_Win;  off = i - 3145728; }
    else                  { src = Wout; dst = g_Wout; off = i - 3932160; }
    float4 x = ((const float4*)src)[off];
    ((float4*)dst)[off] = make_float4(to_tf32(x.x), to_tf32(x.y),
                                      to_tf32(x.z), to_tf32(x.w));
}

// ---------------- tf32 GEMM, 3-stage cp.async (unchanged, known-good) ----------------
#define GT 18432
#define GSTAGE (2 * GT)
#define GSMEM (3 * GSTAGE)

__global__ __launch_bounds__(256, 2) void gemm_tf32(const float* __restrict__ A0,
    const float* __restrict__ A1, const float* __restrict__ A2,
    const float* __restrict__ W,  const float* __restrict__ bias,
    float* __restrict__ Qtf, float* __restrict__ Ktf,
    __nv_bfloat16* __restrict__ Vhb, __nv_bfloat16* __restrict__ Vlb,
    float* __restrict__ Cflat, float scaleQ, int qkv)
{
    extern __shared__ __align__(16) char gsm[];
    const int z = qkv ? blockIdx.z : 0;
    const float* A  = qkv ? (z == 0 ? A0 : (z == 1 ? A1 : A2)) : A0;
    const float* Wz = W + (size_t)z * E_DIM * E_DIM;
    const float* bz = bias + z * E_DIM;
    const int   mode  = qkv ? (z == 2 ? 1 : 2) : 0;
    const float scale = (qkv && z == 0) ? scaleQ : 1.f;
    float* Cf = (z == 0) ? Qtf : Ktf;

    const int tid = threadIdx.x, lane = tid & 31, wid = tid >> 5;
    const int wm = wid >> 2, wn = wid & 3;
    const int bm = blockIdx.y << 7, bn = blockIdx.x << 7;
    const int lrow = lane & 15, lk16 = ((lane >> 4) & 1) << 4;
    const uint32_t uS = smem_u32(gsm);

    float acc[4][4][4];
    #pragma unroll
    for (int i = 0; i < 4; i++)
        #pragma unroll
        for (int j = 0; j < 4; j++)
            #pragma unroll
            for (int r = 0; r < 4; r++) acc[i][j][r] = 0.f;

    const int crow0 = tid >> 3;
    const int cjf   = (tid & 7) << 2;
    const float* gA = A  + (size_t)bm * E_DIM;
    const float* gW = Wz + (size_t)bn * E_DIM;

    #pragma unroll
    for (int s = 0; s < 2; s++) {
        const uint32_t dst = uS + (uint32_t)s * GSTAGE;
        const int kc = s * 32;
        #pragma unroll
        for (int it = 0; it < 4; it++) {
            const int row = crow0 + it * 32;
            const uint32_t off = (uint32_t)row * 144 + (uint32_t)cjf * 4;
            cp_async16(dst + off,      gA + (size_t)row * E_DIM + kc + cjf);
            cp_async16(dst + GT + off, gW + (size_t)row * E_DIM + kc + cjf);
        }
        cp_commit();
    }

    const int NK = E_DIM / 32;
    for (int kt = 0; kt < NK; kt++) {
        cp_wait<1>();
        __syncthreads();
        if (kt + 2 < NK) {
            const uint32_t dst = uS + (uint32_t)((kt + 2) % 3) * GSTAGE;
            const int kc = (kt + 2) * 32;
            #pragma unroll
            for (int it = 0; it < 4; it++) {
                const int row = crow0 + it * 32;
                const uint32_t off = (uint32_t)row * 144 + (uint32_t)cjf * 4;
                cp_async16(dst + off,      gA + (size_t)row * E_DIM + kc + cjf);
                cp_async16(dst + GT + off, gW + (size_t)row * E_DIM + kc + cjf);
            }
        }
        cp_commit();

        const uint32_t pA = uS + (uint32_t)(kt % 3) * GSTAGE;
        const uint32_t pW = pA + GT;
        #pragma unroll
        for (int kk = 0; kk < 4; kk++) {
            uint32_t Af[4][4];
            #pragma unroll
            for (int mt = 0; mt < 4; mt++)
                ldsm4(Af[mt], pA + (uint32_t)(wm * 64 + mt * 16 + lrow) * 144 + kk * 32 + lk16);
            uint32_t Bf[2][4];
            #pragma unroll
            for (int nb = 0; nb < 2; nb++)
                ldsm4(Bf[nb], pW + (uint32_t)(wn * 32 + nb * 16 + lrow) * 144 + kk * 32 + lk16);
            #pragma unroll
            for (int mt = 0; mt < 4; mt++) {
                #pragma unroll
                for (int nt = 0; nt < 4; nt++) {
                    const int nb = nt >> 1, hf = nt & 1;
                    mma_tf32(acc[mt][nt], Af[mt], Bf[nb][hf], Bf[nb][hf + 2]);
                }
            }
        }
    }

    const int g = lane >> 2, tig = lane & 3;
    #pragma unroll
    for (int mt = 0; mt < 4; mt++) {
        #pragma unroll
        for (int nt = 0; nt < 4; nt++) {
            const int m0 = bm + wm * 64 + mt * 16 + g;
            const int n0 = bn + wn * 32 + nt * 8 + tig * 2;
            const float b0 = bz[n0], b1 = bz[n0 + 1];
            float v[4];
            #pragma unroll
            for (int r = 0; r < 4; r++)
                v[r] = (acc[mt][nt][r] + ((r & 1) ? b1 : b0)) * scale;
            if (mode == 1) {
                #pragma unroll
                for (int rr = 0; rr < 2; rr++) {
                    const int m = m0 + rr * 8;
                    const int t = m >> 1, b = m & 1, h = n0 >> 6, dd = n0 & 63;
                    uint32_t hi, lo;
                    split2(v[rr * 2], v[rr * 2 + 1], hi, lo);
                    const size_t idx = (((size_t)(b * H_DIM + h)) * T_DIM + t) * D_DIM + dd;
                    *reinterpret_cast<uint32_t*>(&Vhb[idx]) = hi;
                    *reinterpret_cast<uint32_t*>(&Vlb[idx]) = lo;
                }
            } else if (mode == 2) {
                #pragma unroll
                for (int rr = 0; rr < 2; rr++) {
                    const int m = m0 + rr * 8;
                    const int t = m >> 1, b = m & 1, h = n0 >> 6, dd = n0 & 63;
                    const size_t idx = (((size_t)(b * H_DIM + h)) * T_DIM + t) * D_DIM + dd;
                    *(float2*)(Cf + idx) = make_float2(to_tf32(v[rr * 2]),
                                                       to_tf32(v[rr * 2 + 1]));
                }
            } else {
                #pragma unroll
                for (int r = 0; r < 4; r++) {
                    const int m = m0 + ((r >> 1) << 3);
                    const int n = n0 + (r & 1);
                    Cflat[(size_t)m * E_DIM + n] = v[r];
                }
            }
        }
    }
}

// ---------------- flash attention: 64q, occ 4, single K buffer, split K/V waits ----------------
#define AOFF_Q  0
#define AOFF_K  17408
#define AOFF_VH 34816
#define AOFF_VL 44032
#define ATT_SMEM 53248

__global__ __launch_bounds__(128, 4) void attn_mma(
    const float* __restrict__ Qtf, const float* __restrict__ Ktf,
    const __nv_bfloat16* __restrict__ Vhb, const __nv_bfloat16* __restrict__ Vlb,
    float* __restrict__ ctx)
{
    extern __shared__ __align__(16) char smraw[];
    const int tid = threadIdx.x, lane = tid & 31, w = tid >> 5;
    const int qt = blockIdx.x, hg = blockIdx.y;
    const int lrow = lane & 15, lk16 = ((lane >> 4) & 1) << 4;
    const int rg = lane >> 2, tig = lane & 3;
    const uint32_t uSM = smem_u32(smraw);

    // prologue: Q (group)
    {
        const float* gq = Qtf + ((size_t)hg * T_DIM + qt * 64) * D_DIM;
        #pragma unroll
        for (int i = 0; i < 8; i++) {
            int c = tid + i * 128, row = c >> 4, j = c & 15;
            cp_async16(uSM + AOFF_Q + row * 272 + j * 16, gq + c * 4);
        }
        cp_commit();
    }

    float o[8][4];
    #pragma unroll
    for (int nt = 0; nt < 8; nt++)
        #pragma unroll
        for (int r = 0; r < 4; r++) o[nt][r] = 0.f;
    float m0 = -CUDART_INF_F, m1 = -CUDART_INF_F, l0 = 0.f, l1 = 0.f;

    const float* gK = Ktf + (size_t)hg * T_DIM * D_DIM;
    const __nv_bfloat16* gVh = Vhb + (size_t)hg * T_DIM * D_DIM;
    const __nv_bfloat16* gVl = Vlb + (size_t)hg * T_DIM * D_DIM;

    for (int st = 0; st < T_DIM / 64; st++) {
        __syncthreads();   // prior tile's smem reads done
        // group: K(st)
        #pragma unroll
        for (int i = 0; i < 8; i++) {
            int c = tid + i * 128, row = c >> 4, j = c & 15;
            cp_async16(uSM + AOFF_K + row * 272 + j * 16, gK + (size_t)st * 4096 + c * 4);
        }
        cp_commit();
        // group: V(st)
        #pragma unroll
        for (int i = 0; i < 4; i++) {
            int c = tid + i * 128, row = c >> 3, j = c & 7;
            int off = row * 144 + j * 16;
            cp_async16(uSM + AOFF_VH + off, gVh + (size_t)st * 4096 + c * 8);
            cp_async16(uSM + AOFF_VL + off, gVl + (size_t)st * 4096 + c * 8);
        }
        cp_commit();
        cp_wait<1>();      // K(st) (+Q at st=0) resident; V(st) may be in flight
        __syncthreads();

        // ---- S = Q K^T (tf32) ----
        float s[8][4];
        #pragma unroll
        for (int nt = 0; nt < 8; nt++)
            #pragma unroll
            for (int r = 0; r < 4; r++) s[nt][r] = 0.f;
        #pragma unroll
        for (int kk = 0; kk < 8; kk++) {
            uint32_t qa[4];
            ldsm4(qa, uSM + AOFF_Q + (uint32_t)(w * 16 + lrow) * 272 + kk * 32 + lk16);
            uint32_t kf[4][4];
            #pragma unroll
            for (int nb = 0; nb < 4; nb++)
                ldsm4(kf[nb], uSM + AOFF_K + (uint32_t)(nb * 16 + lrow) * 272 + kk * 32 + lk16);
            #pragma unroll
            for (int nb = 0; nb < 4; nb++) {
                mma_tf32(s[2 * nb],     qa, kf[nb][0], kf[nb][2]);
                mma_tf32(s[2 * nb + 1], qa, kf[nb][1], kf[nb][3]);
            }
        }

        // ---- online softmax (exp2 domain) ----
        float mx0 = -CUDART_INF_F, mx1 = -CUDART_INF_F;
        #pragma unroll
        for (int nt = 0; nt < 8; nt++) {
            mx0 = fmaxf(mx0, fmaxf(s[nt][0], s[nt][1]));
            mx1 = fmaxf(mx1, fmaxf(s[nt][2], s[nt][3]));
        }
        mx0 = fmaxf(mx0, __shfl_xor_sync(~0u, mx0, 1));
        mx0 = fmaxf(mx0, __shfl_xor_sync(~0u, mx0, 2));
        mx1 = fmaxf(mx1, __shfl_xor_sync(~0u, mx1, 1));
        mx1 = fmaxf(mx1, __shfl_xor_sync(~0u, mx1, 2));
        const float mn0 = fmaxf(m0, mx0), mn1 = fmaxf(m1, mx1);
        const float al0 = ex2f(m0 - mn0), al1 = ex2f(m1 - mn1);
        m0 = mn0; m1 = mn1;
        float sum0 = 0.f, sum1 = 0.f;
        #pragma unroll
        for (int nt = 0; nt < 8; nt++) {
            s[nt][0] = ex2f(s[nt][0] - m0); s[nt][1] = ex2f(s[nt][1] - m0);
            s[nt][2] = ex2f(s[nt][2] - m1); s[nt][3] = ex2f(s[nt][3] - m1);
            sum0 += s[nt][0] + s[nt][1];
            sum1 += s[nt][2] + s[nt][3];
        }
        sum0 += __shfl_xor_sync(~0u, sum0, 1); sum0 += __shfl_xor_sync(~0u, sum0, 2);
        sum1 += __shfl_xor_sync(~0u, sum1, 1); sum1 += __shfl_xor_sync(~0u, sum1, 2);
        l0 = l0 * al0 + sum0; l1 = l1 * al1 + sum1;
        #pragma unroll
        for (int nt = 0; nt < 8; nt++) {
            o[nt][0] *= al0; o[nt][1] *= al0; o[nt][2] *= al1; o[nt][3] *= al1;
        }

        // ---- P -> bf16 hi/lo fragments ----
        uint32_t AH[4][4], AL[4][4];
        #pragma unroll
        for (int kb = 0; kb < 4; kb++) {
            const int t0 = 2 * kb, t1 = 2 * kb + 1;
            split2(s[t0][0], s[t0][1], AH[kb][0], AL[kb][0]);
            split2(s[t0][2], s[t0][3], AH[kb][1], AL[kb][1]);
            split2(s[t1][0], s[t1][1], AH[kb][2], AL[kb][2]);
            split2(s[t1][2], s[t1][3], AH[kb][3], AL[kb][3]);
        }

        // ---- wait V(st), then O += P V (bf16x3) ----
        cp_wait<0>();
        __syncthreads();
        #pragma unroll
        for (int kb = 0; kb < 4; kb++) {
            uint32_t vh[4][4], vl[4][4];
            #pragma unroll
            for (int db = 0; db < 4; db++) {
                const uint32_t a = uSM + AOFF_VH + (uint32_t)(kb * 16 + lrow) * 144 + db * 32 + lk16;
                ldsm4t(vh[db], a);
                ldsm4t(vl[db], a + (AOFF_VL - AOFF_VH));
            }
            #pragma unroll
            for (int db = 0; db < 4; db++) {
                #pragma unroll
                for (int hs = 0; hs < 2; hs++) {
                    const int nt = db * 2 + hs;
                    mma_bf16(o[nt], AH[kb], vh[db][hs * 2], vh[db][hs * 2 + 1]);
                    mma_bf16(o[nt], AL[kb], vh[db][hs * 2], vh[db][hs * 2 + 1]);
                    mma_bf16(o[nt], AH[kb], vl[db][hs * 2], vl[db][hs * 2 + 1]);
                }
            }
        }
    }

    // ---- epilogue: tf32-rounded ctx ----
    const float inv0 = 1.f / l0, inv1 = 1.f / l1;
    const int bb = hg >> 4, hh = hg & 15;
    const int q0 = qt * 64 + w * 16 + rg;
    #pragma unroll
    for (int nt = 0; nt < 8; nt++) {
        const int d = hh * 64 + nt * 8 + tig * 2;
        *(float2*)(ctx + ((size_t)q0 * B_DIM + bb) * E_DIM + d) =
            make_float2(to_tf32(o[nt][0] * inv0), to_tf32(o[nt][1] * inv0));
        *(float2*)(ctx + ((size_t)(q0 + 8) * B_DIM + bb) * E_DIM + d) =
            make_float2(to_tf32(o[nt][2] * inv1), to_tf32(o[nt][3] * inv1));
    }
}

// ---------------------------------------------------------------------------
extern "C" void kernel_launch(void* const* d_in, const int* in_sizes, int n_in,
                              void* d_out, int out_size)
{
    const float* query = (const float*)d_in[0];
    const float* key   = (const float*)d_in[1];
    const float* value = (const float*)d_in[2];
    const float* Win   = (const float*)d_in[3];
    const float* bin   = (const float*)d_in[4];
    const float* Wout  = (const float*)d_in[5];
    const float* bout  = (const float*)d_in[6];
    float* out = (float*)d_out;

    float *Qtf, *Ktf, *ctx, *q_r, *k_r, *v_r, *Win_r, *Wout_r;
    __nv_bfloat16 *Vhb, *Vlb;
    cudaGetSymbolAddress((void**)&Qtf,    g_Qtf);
    cudaGetSymbolAddress((void**)&Ktf,    g_Ktf);
    cudaGetSymbolAddress((void**)&Vhb,    g_Vhb);
    cudaGetSymbolAddress((void**)&Vlb,    g_Vlb);
    cudaGetSymbolAddress((void**)&ctx,    g_ctx);
    cudaGetSymbolAddress((void**)&q_r,    g_q);
    cudaGetSymbolAddress((void**)&k_r,    g_k);
    cudaGetSymbolAddress((void**)&v_r,    g_v);
    cudaGetSymbolAddress((void**)&Win_r,  g_Win);
    cudaGetSymbolAddress((void**)&Wout_r, g_Wout);

    const float scaleQ = 0.125f * 1.44269504089f;   // 1/sqrt(64) * log2(e)

    cudaFuncSetAttribute(gemm_tf32, cudaFuncAttributeMaxDynamicSharedMemorySize, GSMEM);
    cudaFuncSetAttribute(attn_mma,  cudaFuncAttributeMaxDynamicSharedMemorySize, ATT_SMEM);

    preround_all<<<16384, 256>>>(query, key, value, Win, Wout);

    gemm_tf32<<<dim3(8, 32, 3), 256, GSMEM>>>(
        q_r, k_r, v_r, Win_r, bin, Qtf, Ktf, Vhb, Vlb, nullptr, scaleQ, 1);

    attn_mma<<<dim3(32, 32), 128, ATT_SMEM>>>(Qtf, Ktf, Vhb, Vlb, ctx);

    gemm_tf32<<<dim3(8, 32, 1), 256, GSMEM>>>(
        ctx, nullptr, nullptr, Wout_r, bout, nullptr, nullptr, nullptr, nullptr, out, 1.f, 0);
}

// round 14
// speedup vs baseline: 1.0508x; 1.0030x over previous
#include <cuda_runtime.h>
#include <cuda_bf16.h>
#include <math_constants.h>
#include <cstdint>

#define T_DIM 2048
#define B_DIM 2
#define E_DIM 1024
#define H_DIM 16
#define D_DIM 64
#define NHEADS 32
#define NROWS  4096

// Scratch (device globals; no runtime allocation)
__device__ float         g_Qtf[NROWS * E_DIM];   // tf32, scale*log2e folded
__device__ float         g_Ktf[NROWS * E_DIM];   // tf32
__device__ __nv_bfloat16 g_Vhb[NROWS * E_DIM], g_Vlb[NROWS * E_DIM];
__device__ float         g_ctx[NROWS * E_DIM];   // tf32-rounded
__device__ float         g_q[NROWS * E_DIM], g_k[NROWS * E_DIM], g_v[NROWS * E_DIM];
__device__ float         g_Win[3 * E_DIM * E_DIM], g_Wout[E_DIM * E_DIM];

// ---------------- helpers ----------------
__device__ __forceinline__ void ldsm4(uint32_t* r, uint32_t a) {
    asm volatile("ldmatrix.sync.aligned.m8n8.x4.shared.b16 {%0,%1,%2,%3}, [%4];"
                 : "=r"(r[0]), "=r"(r[1]), "=r"(r[2]), "=r"(r[3]) : "r"(a));
}
__device__ __forceinline__ void ldsm4t(uint32_t* r, uint32_t a) {
    asm volatile("ldmatrix.sync.aligned.m8n8.x4.trans.shared.b16 {%0,%1,%2,%3}, [%4];"
                 : "=r"(r[0]), "=r"(r[1]), "=r"(r[2]), "=r"(r[3]) : "r"(a));
}
__device__ __forceinline__ void mma_bf16(float* d, const uint32_t* a, uint32_t b0, uint32_t b1) {
    asm volatile("mma.sync.aligned.m16n8k16.row.col.f32.bf16.bf16.f32 "
                 "{%0,%1,%2,%3}, {%4,%5,%6,%7}, {%8,%9}, {%0,%1,%2,%3};"
                 : "+f"(d[0]), "+f"(d[1]), "+f"(d[2]), "+f"(d[3])
                 : "r"(a[0]), "r"(a[1]), "r"(a[2]), "r"(a[3]), "r"(b0), "r"(b1));
}
__device__ __forceinline__ void mma_tf32(float* d, const uint32_t* a, uint32_t b0, uint32_t b1) {
    asm volatile("mma.sync.aligned.m16n8k8.row.col.f32.tf32.tf32.f32 "
                 "{%0,%1,%2,%3}, {%4,%5,%6,%7}, {%8,%9}, {%0,%1,%2,%3};"
                 : "+f"(d[0]), "+f"(d[1]), "+f"(d[2]), "+f"(d[3])
                 : "r"(a[0]), "r"(a[1]), "r"(a[2]), "r"(a[3]), "r"(b0), "r"(b1));
}
__device__ __forceinline__ uint32_t smem_u32(const void* p) {
    return (uint32_t)__cvta_generic_to_shared(p);
}
__device__ __forceinline__ void cp_async16(uint32_t d, const void* s) {
    asm volatile("cp.async.cg.shared.global [%0], [%1], 16;" :: "r"(d), "l"(s));
}
__device__ __forceinline__ void cp_commit() { asm volatile("cp.async.commit_group;"); }
template <int N> __device__ __forceinline__ void cp_wait() {
    asm volatile("cp.async.wait_group %0;" :: "n"(N));
}
__device__ __forceinline__ uint32_t pack_bf16(__nv_bfloat16 x, __nv_bfloat16 y) {
    __nv_bfloat162 v = __halves2bfloat162(x, y);
    return *reinterpret_cast<uint32_t*>(&v);
}
__device__ __forceinline__ void split2(float a, float b, uint32_t& hi, uint32_t& lo) {
    __nv_bfloat16 ha = __float2bfloat16(a), hb = __float2bfloat16(b);
    hi = pack_bf16(ha, hb);
    lo = pack_bf16(__float2bfloat16(a - __bfloat162float(ha)),
                   __float2bfloat16(b - __bfloat162float(hb)));
}
__device__ __forceinline__ float to_tf32(float x) {
    uint32_t r; asm("cvt.rna.tf32.f32 %0, %1;" : "=r"(r) : "f"(x));
    return __uint_as_float(r);
}
__device__ __forceinline__ float ex2f(float x) {
    float y; asm("ex2.approx.ftz.f32 %0, %1;" : "=f"(y) : "f"(x));
    return y;
}

// ---------------- merged tf32-RNA preround (segment ladder, one launch) ----------------
__global__ __launch_bounds__(256) void preround_all(const float* __restrict__ q,
    const float* __restrict__ k, const float* __restrict__ v,
    const float* __restrict__ Win, const float* __restrict__ Wout)
{
    const long i = (long)blockIdx.x * 256 + threadIdx.x;
    const float* src; float* dst; long off;
    if (i < 1048576)      { src = q;    dst = g_q;    off = i; }
    else if (i < 2097152) { src = k;    dst = g_k;    off = i - 1048576; }
    else if (i < 3145728) { src = v;    dst = g_v;    off = i - 2097152; }
    else if (i < 3932160) { src = Win;  dst = g_Win;  off = i - 3145728; }
    else                  { src = Wout; dst = g_Wout; off = i - 3932160; }
    float4 x = ((const float4*)src)[off];
    ((float4*)dst)[off] = make_float4(to_tf32(x.x), to_tf32(x.y),
                                      to_tf32(x.z), to_tf32(x.w));
}

// ---------------- tf32 GEMM: 512 thr / 16 warps (4Mx4N), 2-stage cp.async ----------------
#define GT 18432                   // one tensor tile: 128 rows * 144B
#define GSTAGE (2 * GT)            // A + W
#define GSMEM (2 * GSTAGE)         // 73728

__global__ __launch_bounds__(512, 2) void gemm_tf32(const float* __restrict__ A0,
    const float* __restrict__ A1, const float* __restrict__ A2,
    const float* __restrict__ W,  const float* __restrict__ bias,
    float* __restrict__ Qtf, float* __restrict__ Ktf,
    __nv_bfloat16* __restrict__ Vhb, __nv_bfloat16* __restrict__ Vlb,
    float* __restrict__ Cflat, float scaleQ, int qkv)
{
    extern __shared__ __align__(16) char gsm[];
    const int z = qkv ? blockIdx.z : 0;
    const float* A  = qkv ? (z == 0 ? A0 : (z == 1 ? A1 : A2)) : A0;
    const float* Wz = W + (size_t)z * E_DIM * E_DIM;
    const float* bz = bias + z * E_DIM;
    const int   mode  = qkv ? (z == 2 ? 1 : 2) : 0;
    const float scale = (qkv && z == 0) ? scaleQ : 1.f;
    float* Cf = (z == 0) ? Qtf : Ktf;

    const int tid = threadIdx.x, lane = tid & 31, wid = tid >> 5;
    const int wm = wid >> 2, wn = wid & 3;           // 4x4 warp grid, 32x32 each
    const int bm = blockIdx.y << 7, bn = blockIdx.x << 7;
    const int lrow = lane & 15, lk16 = ((lane >> 4) & 1) << 4;
    const uint32_t uS = smem_u32(gsm);

    float acc[2][4][4];
    #pragma unroll
    for (int i = 0; i < 2; i++)
        #pragma unroll
        for (int j = 0; j < 4; j++)
            #pragma unroll
            for (int r = 0; r < 4; r++) acc[i][j][r] = 0.f;

    // copy mapping: 1024 16B-chunks per tensor tile, 2 per thread
    const float* gA = A  + (size_t)bm * E_DIM;
    const float* gW = Wz + (size_t)bn * E_DIM;

    // prologue: stages 0, 1
    #pragma unroll
    for (int s = 0; s < 2; s++) {
        const uint32_t dst = uS + (uint32_t)s * GSTAGE;
        const int kc = s * 32;
        #pragma unroll
        for (int it = 0; it < 2; it++) {
            const int idx = tid + it * 512;
            const int row = idx >> 3, j = idx & 7;
            const uint32_t off = (uint32_t)row * 144 + (uint32_t)(j * 16);
            cp_async16(dst + off,      gA + (size_t)row * E_DIM + kc + j * 4);
            cp_async16(dst + GT + off, gW + (size_t)row * E_DIM + kc + j * 4);
        }
        cp_commit();
    }

    const int NK = E_DIM / 32;   // 32
    for (int kt = 0; kt < NK; kt++) {
        cp_wait<1>();            // stage kt resident
        __syncthreads();

        const uint32_t pA = uS + (uint32_t)(kt & 1) * GSTAGE;
        const uint32_t pW = pA + GT;
        #pragma unroll
        for (int kk = 0; kk < 4; kk++) {
            uint32_t Af[2][4];
            #pragma unroll
            for (int mt = 0; mt < 2; mt++)
                ldsm4(Af[mt], pA + (uint32_t)(wm * 32 + mt * 16 + lrow) * 144 + kk * 32 + lk16);
            uint32_t Bf[2][4];
            #pragma unroll
            for (int nb = 0; nb < 2; nb++)
                ldsm4(Bf[nb], pW + (uint32_t)(wn * 32 + nb * 16 + lrow) * 144 + kk * 32 + lk16);
            #pragma unroll
            for (int mt = 0; mt < 2; mt++) {
                #pragma unroll
                for (int nt = 0; nt < 4; nt++) {
                    const int nb = nt >> 1, hf = nt & 1;
                    mma_tf32(acc[mt][nt], Af[mt], Bf[nb][hf], Bf[nb][hf + 2]);
                }
            }
        }

        __syncthreads();         // all reads of buf kt&1 done before refill
        if (kt + 2 < NK) {
            const uint32_t dst = uS + (uint32_t)(kt & 1) * GSTAGE;
            const int kc = (kt + 2) * 32;
            #pragma unroll
            for (int it = 0; it < 2; it++) {
                const int idx = tid + it * 512;
                const int row = idx >> 3, j = idx & 7;
                const uint32_t off = (uint32_t)row * 144 + (uint32_t)(j * 16);
                cp_async16(dst + off,      gA + (size_t)row * E_DIM + kc + j * 4);
                cp_async16(dst + GT + off, gW + (size_t)row * E_DIM + kc + j * 4);
            }
        }
        cp_commit();             // empty group when no loads keeps counts uniform
    }

    // ---- epilogue ----
    const int g = lane >> 2, tig = lane & 3;
    #pragma unroll
    for (int mt = 0; mt < 2; mt++) {
        #pragma unroll
        for (int nt = 0; nt < 4; nt++) {
            const int m0 = bm + wm * 32 + mt * 16 + g;
            const int n0 = bn + wn * 32 + nt * 8 + tig * 2;
            const float b0 = bz[n0], b1 = bz[n0 + 1];
            float v[4];
            #pragma unroll
            for (int r = 0; r < 4; r++)
                v[r] = (acc[mt][nt][r] + ((r & 1) ? b1 : b0)) * scale;
            if (mode == 1) {
                #pragma unroll
                for (int rr = 0; rr < 2; rr++) {
                    const int m = m0 + rr * 8;
                    const int t = m >> 1, b = m & 1, h = n0 >> 6, dd = n0 & 63;
                    uint32_t hi, lo;
                    split2(v[rr * 2], v[rr * 2 + 1], hi, lo);
                    const size_t idx = (((size_t)(b * H_DIM + h)) * T_DIM + t) * D_DIM + dd;
                    *reinterpret_cast<uint32_t*>(&Vhb[idx]) = hi;
                    *reinterpret_cast<uint32_t*>(&Vlb[idx]) = lo;
                }
            } else if (mode == 2) {
                #pragma unroll
                for (int rr = 0; rr < 2; rr++) {
                    const int m = m0 + rr * 8;
                    const int t = m >> 1, b = m & 1, h = n0 >> 6, dd = n0 & 63;
                    const size_t idx = (((size_t)(b * H_DIM + h)) * T_DIM + t) * D_DIM + dd;
                    *(float2*)(Cf + idx) = make_float2(to_tf32(v[rr * 2]),
                                                       to_tf32(v[rr * 2 + 1]));
                }
            } else {
                #pragma unroll
                for (int r = 0; r < 4; r++) {
                    const int m = m0 + ((r >> 1) << 3);
                    const int n = n0 + (r & 1);
                    Cflat[(size_t)m * E_DIM + n] = v[r];
                }
            }
        }
    }
}

// ---------------- flash attention: 64q, occ 4, single K buffer, split K/V waits ----------------
#define AOFF_Q  0
#define AOFF_K  17408
#define AOFF_VH 34816
#define AOFF_VL 44032
#define ATT_SMEM 53248

__global__ __launch_bounds__(128, 4) void attn_mma(
    const float* __restrict__ Qtf, const float* __restrict__ Ktf,
    const __nv_bfloat16* __restrict__ Vhb, const __nv_bfloat16* __restrict__ Vlb,
    float* __restrict__ ctx)
{
    extern __shared__ __align__(16) char smraw[];
    const int tid = threadIdx.x, lane = tid & 31, w = tid >> 5;
    const int qt = blockIdx.x, hg = blockIdx.y;
    const int lrow = lane & 15, lk16 = ((lane >> 4) & 1) << 4;
    const int rg = lane >> 2, tig = lane & 3;
    const uint32_t uSM = smem_u32(smraw);

    {
        const float* gq = Qtf + ((size_t)hg * T_DIM + qt * 64) * D_DIM;
        #pragma unroll
        for (int i = 0; i < 8; i++) {
            int c = tid + i * 128, row = c >> 4, j = c & 15;
            cp_async16(uSM + AOFF_Q + row * 272 + j * 16, gq + c * 4);
        }
        cp_commit();
    }

    float o[8][4];
    #pragma unroll
    for (int nt = 0; nt < 8; nt++)
        #pragma unroll
        for (int r = 0; r < 4; r++) o[nt][r] = 0.f;
    float m0 = -CUDART_INF_F, m1 = -CUDART_INF_F, l0 = 0.f, l1 = 0.f;

    const float* gK = Ktf + (size_t)hg * T_DIM * D_DIM;
    const __nv_bfloat16* gVh = Vhb + (size_t)hg * T_DIM * D_DIM;
    const __nv_bfloat16* gVl = Vlb + (size_t)hg * T_DIM * D_DIM;

    for (int st = 0; st < T_DIM / 64; st++) {
        __syncthreads();
        #pragma unroll
        for (int i = 0; i < 8; i++) {
            int c = tid + i * 128, row = c >> 4, j = c & 15;
            cp_async16(uSM + AOFF_K + row * 272 + j * 16, gK + (size_t)st * 4096 + c * 4);
        }
        cp_commit();
        #pragma unroll
        for (int i = 0; i < 4; i++) {
            int c = tid + i * 128, row = c >> 3, j = c & 7;
            int off = row * 144 + j * 16;
            cp_async16(uSM + AOFF_VH + off, gVh + (size_t)st * 4096 + c * 8);
            cp_async16(uSM + AOFF_VL + off, gVl + (size_t)st * 4096 + c * 8);
        }
        cp_commit();
        cp_wait<1>();
        __syncthreads();

        float s[8][4];
        #pragma unroll
        for (int nt = 0; nt < 8; nt++)
            #pragma unroll
            for (int r = 0; r < 4; r++) s[nt][r] = 0.f;
        #pragma unroll
        for (int kk = 0; kk < 8; kk++) {
            uint32_t qa[4];
            ldsm4(qa, uSM + AOFF_Q + (uint32_t)(w * 16 + lrow) * 272 + kk * 32 + lk16);
            uint32_t kf[4][4];
            #pragma unroll
            for (int nb = 0; nb < 4; nb++)
                ldsm4(kf[nb], uSM + AOFF_K + (uint32_t)(nb * 16 + lrow) * 272 + kk * 32 + lk16);
            #pragma unroll
            for (int nb = 0; nb < 4; nb++) {
                mma_tf32(s[2 * nb],     qa, kf[nb][0], kf[nb][2]);
                mma_tf32(s[2 * nb + 1], qa, kf[nb][1], kf[nb][3]);
            }
        }

        float mx0 = -CUDART_INF_F, mx1 = -CUDART_INF_F;
        #pragma unroll
        for (int nt = 0; nt < 8; nt++) {
            mx0 = fmaxf(mx0, fmaxf(s[nt][0], s[nt][1]));
            mx1 = fmaxf(mx1, fmaxf(s[nt][2], s[nt][3]));
        }
        mx0 = fmaxf(mx0, __shfl_xor_sync(~0u, mx0, 1));
        mx0 = fmaxf(mx0, __shfl_xor_sync(~0u, mx0, 2));
        mx1 = fmaxf(mx1, __shfl_xor_sync(~0u, mx1, 1));
        mx1 = fmaxf(mx1, __shfl_xor_sync(~0u, mx1, 2));
        const float mn0 = fmaxf(m0, mx0), mn1 = fmaxf(m1, mx1);
        const float al0 = ex2f(m0 - mn0), al1 = ex2f(m1 - mn1);
        m0 = mn0; m1 = mn1;
        float sum0 = 0.f, sum1 = 0.f;
        #pragma unroll
        for (int nt = 0; nt < 8; nt++) {
            s[nt][0] = ex2f(s[nt][0] - m0); s[nt][1] = ex2f(s[nt][1] - m0);
            s[nt][2] = ex2f(s[nt][2] - m1); s[nt][3] = ex2f(s[nt][3] - m1);
            sum0 += s[nt][0] + s[nt][1];
            sum1 += s[nt][2] + s[nt][3];
        }
        sum0 += __shfl_xor_sync(~0u, sum0, 1); sum0 += __shfl_xor_sync(~0u, sum0, 2);
        sum1 += __shfl_xor_sync(~0u, sum1, 1); sum1 += __shfl_xor_sync(~0u, sum1, 2);
        l0 = l0 * al0 + sum0; l1 = l1 * al1 + sum1;
        #pragma unroll
        for (int nt = 0; nt < 8; nt++) {
            o[nt][0] *= al0; o[nt][1] *= al0; o[nt][2] *= al1; o[nt][3] *= al1;
        }

        uint32_t AH[4][4], AL[4][4];
        #pragma unroll
        for (int kb = 0; kb < 4; kb++) {
            const int t0 = 2 * kb, t1 = 2 * kb + 1;
            split2(s[t0][0], s[t0][1], AH[kb][0], AL[kb][0]);
            split2(s[t0][2], s[t0][3], AH[kb][1], AL[kb][1]);
            split2(s[t1][0], s[t1][1], AH[kb][2], AL[kb][2]);
            split2(s[t1][2], s[t1][3], AH[kb][3], AL[kb][3]);
        }

        cp_wait<0>();
        __syncthreads();
        #pragma unroll
        for (int kb = 0; kb < 4; kb++) {
            uint32_t vh[4][4], vl[4][4];
            #pragma unroll
            for (int db = 0; db < 4; db++) {
                const uint32_t a = uSM + AOFF_VH + (uint32_t)(kb * 16 + lrow) * 144 + db * 32 + lk16;
                ldsm4t(vh[db], a);
                ldsm4t(vl[db], a + (AOFF_VL - AOFF_VH));
            }
            #pragma unroll
            for (int db = 0; db < 4; db++) {
                #pragma unroll
                for (int hs = 0; hs < 2; hs++) {
                    const int nt = db * 2 + hs;
                    mma_bf16(o[nt], AH[kb], vh[db][hs * 2], vh[db][hs * 2 + 1]);
                    mma_bf16(o[nt], AL[kb], vh[db][hs * 2], vh[db][hs * 2 + 1]);
                    mma_bf16(o[nt], AH[kb], vl[db][hs * 2], vl[db][hs * 2 + 1]);
                }
            }
        }
    }

    const float inv0 = 1.f / l0, inv1 = 1.f / l1;
    const int bb = hg >> 4, hh = hg & 15;
    const int q0 = qt * 64 + w * 16 + rg;
    #pragma unroll
    for (int nt = 0; nt < 8; nt++) {
        const int d = hh * 64 + nt * 8 + tig * 2;
        *(float2*)(ctx + ((size_t)q0 * B_DIM + bb) * E_DIM + d) =
            make_float2(to_tf32(o[nt][0] * inv0), to_tf32(o[nt][1] * inv0));
        *(float2*)(ctx + ((size_t)(q0 + 8) * B_DIM + bb) * E_DIM + d) =
            make_float2(to_tf32(o[nt][2] * inv1), to_tf32(o[nt][3] * inv1));
    }
}

// ---------------------------------------------------------------------------
extern "C" void kernel_launch(void* const* d_in, const int* in_sizes, int n_in,
                              void* d_out, int out_size)
{
    const float* query = (const float*)d_in[0];
    const float* key   = (const float*)d_in[1];
    const float* value = (const float*)d_in[2];
    const float* Win   = (const float*)d_in[3];
    const float* bin   = (const float*)d_in[4];
    const float* Wout  = (const float*)d_in[5];
    const float* bout  = (const float*)d_in[6];
    float* out = (float*)d_out;

    float *Qtf, *Ktf, *ctx, *q_r, *k_r, *v_r, *Win_r, *Wout_r;
    __nv_bfloat16 *Vhb, *Vlb;
    cudaGetSymbolAddress((void**)&Qtf,    g_Qtf);
    cudaGetSymbolAddress((void**)&Ktf,    g_Ktf);
    cudaGetSymbolAddress((void**)&Vhb,    g_Vhb);
    cudaGetSymbolAddress((void**)&Vlb,    g_Vlb);
    cudaGetSymbolAddress((void**)&ctx,    g_ctx);
    cudaGetSymbolAddress((void**)&q_r,    g_q);
    cudaGetSymbolAddress((void**)&k_r,    g_k);
    cudaGetSymbolAddress((void**)&v_r,    g_v);
    cudaGetSymbolAddress((void**)&Win_r,  g_Win);
    cudaGetSymbolAddress((void**)&Wout_r, g_Wout);

    const float scaleQ = 0.125f * 1.44269504089f;   // 1/sqrt(64) * log2(e)

    cudaFuncSetAttribute(gemm_tf32, cudaFuncAttributeMaxDynamicSharedMemorySize, GSMEM);
    cudaFuncSetAttribute(attn_mma,  cudaFuncAttributeMaxDynamicSharedMemorySize, ATT_SMEM);

    preround_all<<<16384, 256>>>(query, key, value, Win, Wout);

    gemm_tf32<<<dim3(8, 32, 3), 512, GSMEM>>>(
        q_r, k_r, v_r, Win_r, bin, Qtf, Ktf, Vhb, Vlb, nullptr, scaleQ, 1);

    attn_mma<<<dim3(32, 32), 128, ATT_SMEM>>>(Qtf, Ktf, Vhb, Vlb, ctx);

    gemm_tf32<<<dim3(8, 32, 1), 512, GSMEM>>>(
        ctx, nullptr, nullptr, Wout_r, bout, nullptr, nullptr, nullptr, nullptr, out, 1.f, 0);
}

// round 15
// speedup vs baseline: 1.1668x; 1.1104x over previous
#include <cuda_runtime.h>
#include <cuda_bf16.h>
#include <math_constants.h>
#include <cstdint>

#define T_DIM 2048
#define B_DIM 2
#define E_DIM 1024
#define H_DIM 16
#define D_DIM 64
#define NHEADS 32
#define NROWS  4096

// Scratch (device globals; no runtime allocation)
__device__ float         g_Qtf[NROWS * E_DIM];   // tf32, scale*log2e folded
__device__ float         g_Ktf[NROWS * E_DIM];   // tf32
__device__ __nv_bfloat16 g_Vhb[NROWS * E_DIM];
__device__ float         g_ctx[NROWS * E_DIM];   // tf32-rounded
__device__ float         g_q[NROWS * E_DIM], g_k[NROWS * E_DIM], g_v[NROWS * E_DIM];
__device__ float         g_Win[3 * E_DIM * E_DIM], g_Wout[E_DIM * E_DIM];

// ---------------- helpers ----------------
__device__ __forceinline__ void ldsm4(uint32_t* r, uint32_t a) {
    asm volatile("ldmatrix.sync.aligned.m8n8.x4.shared.b16 {%0,%1,%2,%3}, [%4];"
                 : "=r"(r[0]), "=r"(r[1]), "=r"(r[2]), "=r"(r[3]) : "r"(a));
}
__device__ __forceinline__ void ldsm4t(uint32_t* r, uint32_t a) {
    asm volatile("ldmatrix.sync.aligned.m8n8.x4.trans.shared.b16 {%0,%1,%2,%3}, [%4];"
                 : "=r"(r[0]), "=r"(r[1]), "=r"(r[2]), "=r"(r[3]) : "r"(a));
}
__device__ __forceinline__ void mma_bf16(float* d, const uint32_t* a, uint32_t b0, uint32_t b1) {
    asm volatile("mma.sync.aligned.m16n8k16.row.col.f32.bf16.bf16.f32 "
                 "{%0,%1,%2,%3}, {%4,%5,%6,%7}, {%8,%9}, {%0,%1,%2,%3};"
                 : "+f"(d[0]), "+f"(d[1]), "+f"(d[2]), "+f"(d[3])
                 : "r"(a[0]), "r"(a[1]), "r"(a[2]), "r"(a[3]), "r"(b0), "r"(b1));
}
__device__ __forceinline__ void mma_tf32(float* d, const uint32_t* a, uint32_t b0, uint32_t b1) {
    asm volatile("mma.sync.aligned.m16n8k8.row.col.f32.tf32.tf32.f32 "
                 "{%0,%1,%2,%3}, {%4,%5,%6,%7}, {%8,%9}, {%0,%1,%2,%3};"
                 : "+f"(d[0]), "+f"(d[1]), "+f"(d[2]), "+f"(d[3])
                 : "r"(a[0]), "r"(a[1]), "r"(a[2]), "r"(a[3]), "r"(b0), "r"(b1));
}
__device__ __forceinline__ uint32_t smem_u32(const void* p) {
    return (uint32_t)__cvta_generic_to_shared(p);
}
__device__ __forceinline__ void cp_async16(uint32_t d, const void* s) {
    asm volatile("cp.async.cg.shared.global [%0], [%1], 16;" :: "r"(d), "l"(s));
}
__device__ __forceinline__ void cp_commit() { asm volatile("cp.async.commit_group;"); }
template <int N> __device__ __forceinline__ void cp_wait() {
    asm volatile("cp.async.wait_group %0;" :: "n"(N));
}
__device__ __forceinline__ uint32_t pack_bf16(__nv_bfloat16 x, __nv_bfloat16 y) {
    __nv_bfloat162 v = __halves2bfloat162(x, y);
    return *reinterpret_cast<uint32_t*>(&v);
}
__device__ __forceinline__ void split2(float a, float b, uint32_t& hi, uint32_t& lo) {
    __nv_bfloat16 ha = __float2bfloat16(a), hb = __float2bfloat16(b);
    hi = pack_bf16(ha, hb);
    lo = pack_bf16(__float2bfloat16(a - __bfloat162float(ha)),
                   __float2bfloat16(b - __bfloat162float(hb)));
}
__device__ __forceinline__ float to_tf32(float x) {
    uint32_t r; asm("cvt.rna.tf32.f32 %0, %1;" : "=r"(r) : "f"(x));
    return __uint_as_float(r);
}
__device__ __forceinline__ float ex2f(float x) {
    float y; asm("ex2.approx.ftz.f32 %0, %1;" : "=f"(y) : "f"(x));
    return y;
}

// ---------------- merged tf32-RNA preround (segment ladder, one launch) ----------------
__global__ __launch_bounds__(256) void preround_all(const float* __restrict__ q,
    const float* __restrict__ k, const float* __restrict__ v,
    const float* __restrict__ Win, const float* __restrict__ Wout)
{
    const long i = (long)blockIdx.x * 256 + threadIdx.x;
    const float* src; float* dst; long off;
    if (i < 1048576)      { src = q;    dst = g_q;    off = i; }
    else if (i < 2097152) { src = k;    dst = g_k;    off = i - 1048576; }
    else if (i < 3145728) { src = v;    dst = g_v;    off = i - 2097152; }
    else if (i < 3932160) { src = Win;  dst = g_Win;  off = i - 3145728; }
    else                  { src = Wout; dst = g_Wout; off = i - 3932160; }
    float4 x = ((const float4*)src)[off];
    ((float4*)dst)[off] = make_float4(to_tf32(x.x), to_tf32(x.y),
                                      to_tf32(x.z), to_tf32(x.w));
}

// ---------------- tf32 GEMM: 512 thr / 16 warps (4Mx4N), 2-stage cp.async ----------------
#define GT 18432
#define GSTAGE (2 * GT)
#define GSMEM (2 * GSTAGE)

__global__ __launch_bounds__(512, 2) void gemm_tf32(const float* __restrict__ A0,
    const float* __restrict__ A1, const float* __restrict__ A2,
    const float* __restrict__ W,  const float* __restrict__ bias,
    float* __restrict__ Qtf, float* __restrict__ Ktf,
    __nv_bfloat16* __restrict__ Vhb,
    float* __restrict__ Cflat, float scaleQ, int qkv)
{
    extern __shared__ __align__(16) char gsm[];
    const int z = qkv ? blockIdx.z : 0;
    const float* A  = qkv ? (z == 0 ? A0 : (z == 1 ? A1 : A2)) : A0;
    const float* Wz = W + (size_t)z * E_DIM * E_DIM;
    const float* bz = bias + z * E_DIM;
    const int   mode  = qkv ? (z == 2 ? 1 : 2) : 0;
    const float scale = (qkv && z == 0) ? scaleQ : 1.f;
    float* Cf = (z == 0) ? Qtf : Ktf;

    const int tid = threadIdx.x, lane = tid & 31, wid = tid >> 5;
    const int wm = wid >> 2, wn = wid & 3;
    const int bm = blockIdx.y << 7, bn = blockIdx.x << 7;
    const int lrow = lane & 15, lk16 = ((lane >> 4) & 1) << 4;
    const uint32_t uS = smem_u32(gsm);

    float acc[2][4][4];
    #pragma unroll
    for (int i = 0; i < 2; i++)
        #pragma unroll
        for (int j = 0; j < 4; j++)
            #pragma unroll
            for (int r = 0; r < 4; r++) acc[i][j][r] = 0.f;

    const float* gA = A  + (size_t)bm * E_DIM;
    const float* gW = Wz + (size_t)bn * E_DIM;

    #pragma unroll
    for (int s = 0; s < 2; s++) {
        const uint32_t dst = uS + (uint32_t)s * GSTAGE;
        const int kc = s * 32;
        #pragma unroll
        for (int it = 0; it < 2; it++) {
            const int idx = tid + it * 512;
            const int row = idx >> 3, j = idx & 7;
            const uint32_t off = (uint32_t)row * 144 + (uint32_t)(j * 16);
            cp_async16(dst + off,      gA + (size_t)row * E_DIM + kc + j * 4);
            cp_async16(dst + GT + off, gW + (size_t)row * E_DIM + kc + j * 4);
        }
        cp_commit();
    }

    const int NK = E_DIM / 32;
    for (int kt = 0; kt < NK; kt++) {
        cp_wait<1>();
        __syncthreads();

        const uint32_t pA = uS + (uint32_t)(kt & 1) * GSTAGE;
        const uint32_t pW = pA + GT;
        #pragma unroll
        for (int kk = 0; kk < 4; kk++) {
            uint32_t Af[2][4];
            #pragma unroll
            for (int mt = 0; mt < 2; mt++)
                ldsm4(Af[mt], pA + (uint32_t)(wm * 32 + mt * 16 + lrow) * 144 + kk * 32 + lk16);
            uint32_t Bf[2][4];
            #pragma unroll
            for (int nb = 0; nb < 2; nb++)
                ldsm4(Bf[nb], pW + (uint32_t)(wn * 32 + nb * 16 + lrow) * 144 + kk * 32 + lk16);
            #pragma unroll
            for (int mt = 0; mt < 2; mt++) {
                #pragma unroll
                for (int nt = 0; nt < 4; nt++) {
                    const int nb = nt >> 1, hf = nt & 1;
                    mma_tf32(acc[mt][nt], Af[mt], Bf[nb][hf], Bf[nb][hf + 2]);
                }
            }
        }

        __syncthreads();
        if (kt + 2 < NK) {
            const uint32_t dst = uS + (uint32_t)(kt & 1) * GSTAGE;
            const int kc = (kt + 2) * 32;
            #pragma unroll
            for (int it = 0; it < 2; it++) {
                const int idx = tid + it * 512;
                const int row = idx >> 3, j = idx & 7;
                const uint32_t off = (uint32_t)row * 144 + (uint32_t)(j * 16);
                cp_async16(dst + off,      gA + (size_t)row * E_DIM + kc + j * 4);
                cp_async16(dst + GT + off, gW + (size_t)row * E_DIM + kc + j * 4);
            }
        }
        cp_commit();
    }

    // ---- epilogue ----
    const int g = lane >> 2, tig = lane & 3;
    #pragma unroll
    for (int mt = 0; mt < 2; mt++) {
        #pragma unroll
        for (int nt = 0; nt < 4; nt++) {
            const int m0 = bm + wm * 32 + mt * 16 + g;
            const int n0 = bn + wn * 32 + nt * 8 + tig * 2;
            const float b0 = bz[n0], b1 = bz[n0 + 1];
            float v[4];
            #pragma unroll
            for (int r = 0; r < 4; r++)
                v[r] = (acc[mt][nt][r] + ((r & 1) ? b1 : b0)) * scale;
            if (mode == 1) {
                #pragma unroll
                for (int rr = 0; rr < 2; rr++) {
                    const int m = m0 + rr * 8;
                    const int t = m >> 1, b = m & 1, h = n0 >> 6, dd = n0 & 63;
                    const size_t idx = (((size_t)(b * H_DIM + h)) * T_DIM + t) * D_DIM + dd;
                    *reinterpret_cast<uint32_t*>(&Vhb[idx]) =
                        pack_bf16(__float2bfloat16(v[rr * 2]), __float2bfloat16(v[rr * 2 + 1]));
                }
            } else if (mode == 2) {
                #pragma unroll
                for (int rr = 0; rr < 2; rr++) {
                    const int m = m0 + rr * 8;
                    const int t = m >> 1, b = m & 1, h = n0 >> 6, dd = n0 & 63;
                    const size_t idx = (((size_t)(b * H_DIM + h)) * T_DIM + t) * D_DIM + dd;
                    *(float2*)(Cf + idx) = make_float2(to_tf32(v[rr * 2]),
                                                       to_tf32(v[rr * 2 + 1]));
                }
            } else {
                #pragma unroll
                for (int r = 0; r < 4; r++) {
                    const int m = m0 + ((r >> 1) << 3);
                    const int n = n0 + (r & 1);
                    Cflat[(size_t)m * E_DIM + n] = v[r];
                }
            }
        }
    }
}

// ---------------- flash attention: 64q, occ 4, PV 2-pass (Ph*Vh + Pl*Vh) ----------------
#define AOFF_Q  0
#define AOFF_K  17408
#define AOFF_VH 34816
#define ATT_SMEM 44032

__global__ __launch_bounds__(128, 4) void attn_mma(
    const float* __restrict__ Qtf, const float* __restrict__ Ktf,
    const __nv_bfloat16* __restrict__ Vhb,
    float* __restrict__ ctx)
{
    extern __shared__ __align__(16) char smraw[];
    const int tid = threadIdx.x, lane = tid & 31, w = tid >> 5;
    const int qt = blockIdx.x, hg = blockIdx.y;
    const int lrow = lane & 15, lk16 = ((lane >> 4) & 1) << 4;
    const int rg = lane >> 2, tig = lane & 3;
    const uint32_t uSM = smem_u32(smraw);

    {
        const float* gq = Qtf + ((size_t)hg * T_DIM + qt * 64) * D_DIM;
        #pragma unroll
        for (int i = 0; i < 8; i++) {
            int c = tid + i * 128, row = c >> 4, j = c & 15;
            cp_async16(uSM + AOFF_Q + row * 272 + j * 16, gq + c * 4);
        }
        cp_commit();
    }

    float o[8][4];
    #pragma unroll
    for (int nt = 0; nt < 8; nt++)
        #pragma unroll
        for (int r = 0; r < 4; r++) o[nt][r] = 0.f;
    float m0 = -CUDART_INF_F, m1 = -CUDART_INF_F, l0 = 0.f, l1 = 0.f;

    const float* gK = Ktf + (size_t)hg * T_DIM * D_DIM;
    const __nv_bfloat16* gVh = Vhb + (size_t)hg * T_DIM * D_DIM;

    for (int st = 0; st < T_DIM / 64; st++) {
        __syncthreads();
        #pragma unroll
        for (int i = 0; i < 8; i++) {
            int c = tid + i * 128, row = c >> 4, j = c & 15;
            cp_async16(uSM + AOFF_K + row * 272 + j * 16, gK + (size_t)st * 4096 + c * 4);
        }
        cp_commit();
        #pragma unroll
        for (int i = 0; i < 4; i++) {
            int c = tid + i * 128, row = c >> 3, j = c & 7;
            cp_async16(uSM + AOFF_VH + row * 144 + j * 16, gVh + (size_t)st * 4096 + c * 8);
        }
        cp_commit();
        cp_wait<1>();      // K(st) (+Q at st=0) resident; V in flight
        __syncthreads();

        float s[8][4];
        #pragma unroll
        for (int nt = 0; nt < 8; nt++)
            #pragma unroll
            for (int r = 0; r < 4; r++) s[nt][r] = 0.f;
        #pragma unroll
        for (int kk = 0; kk < 8; kk++) {
            uint32_t qa[4];
            ldsm4(qa, uSM + AOFF_Q + (uint32_t)(w * 16 + lrow) * 272 + kk * 32 + lk16);
            uint32_t kf[4][4];
            #pragma unroll
            for (int nb = 0; nb < 4; nb++)
                ldsm4(kf[nb], uSM + AOFF_K + (uint32_t)(nb * 16 + lrow) * 272 + kk * 32 + lk16);
            #pragma unroll
            for (int nb = 0; nb < 4; nb++) {
                mma_tf32(s[2 * nb],     qa, kf[nb][0], kf[nb][2]);
                mma_tf32(s[2 * nb + 1], qa, kf[nb][1], kf[nb][3]);
            }
        }

        float mx0 = -CUDART_INF_F, mx1 = -CUDART_INF_F;
        #pragma unroll
        for (int nt = 0; nt < 8; nt++) {
            mx0 = fmaxf(mx0, fmaxf(s[nt][0], s[nt][1]));
            mx1 = fmaxf(mx1, fmaxf(s[nt][2], s[nt][3]));
        }
        mx0 = fmaxf(mx0, __shfl_xor_sync(~0u, mx0, 1));
        mx0 = fmaxf(mx0, __shfl_xor_sync(~0u, mx0, 2));
        mx1 = fmaxf(mx1, __shfl_xor_sync(~0u, mx1, 1));
        mx1 = fmaxf(mx1, __shfl_xor_sync(~0u, mx1, 2));
        const float mn0 = fmaxf(m0, mx0), mn1 = fmaxf(m1, mx1);
        const float al0 = ex2f(m0 - mn0), al1 = ex2f(m1 - mn1);
        m0 = mn0; m1 = mn1;
        float sum0 = 0.f, sum1 = 0.f;
        #pragma unroll
        for (int nt = 0; nt < 8; nt++) {
            s[nt][0] = ex2f(s[nt][0] - m0); s[nt][1] = ex2f(s[nt][1] - m0);
            s[nt][2] = ex2f(s[nt][2] - m1); s[nt][3] = ex2f(s[nt][3] - m1);
            sum0 += s[nt][0] + s[nt][1];
            sum1 += s[nt][2] + s[nt][3];
        }
        sum0 += __shfl_xor_sync(~0u, sum0, 1); sum0 += __shfl_xor_sync(~0u, sum0, 2);
        sum1 += __shfl_xor_sync(~0u, sum1, 1); sum1 += __shfl_xor_sync(~0u, sum1, 2);
        l0 = l0 * al0 + sum0; l1 = l1 * al1 + sum1;
        #pragma unroll
        for (int nt = 0; nt < 8; nt++) {
            o[nt][0] *= al0; o[nt][1] *= al0; o[nt][2] *= al1; o[nt][3] *= al1;
        }

        uint32_t AH[4][4], AL[4][4];
        #pragma unroll
        for (int kb = 0; kb < 4; kb++) {
            const int t0 = 2 * kb, t1 = 2 * kb + 1;
            split2(s[t0][0], s[t0][1], AH[kb][0], AL[kb][0]);
            split2(s[t0][2], s[t0][3], AH[kb][1], AL[kb][1]);
            split2(s[t1][0], s[t1][1], AH[kb][2], AL[kb][2]);
            split2(s[t1][2], s[t1][3], AH[kb][3], AL[kb][3]);
        }

        cp_wait<0>();      // V(st) resident
        __syncthreads();
        #pragma unroll
        for (int kb = 0; kb < 4; kb++) {
            uint32_t vh[4][4];
            #pragma unroll
            for (int db = 0; db < 4; db++)
                ldsm4t(vh[db], uSM + AOFF_VH + (uint32_t)(kb * 16 + lrow) * 144 + db * 32 + lk16);
            #pragma unroll
            for (int db = 0; db < 4; db++) {
                #pragma unroll
                for (int hs = 0; hs < 2; hs++) {
                    const int nt = db * 2 + hs;
                    mma_bf16(o[nt], AH[kb], vh[db][hs * 2], vh[db][hs * 2 + 1]);
                    mma_bf16(o[nt], AL[kb], vh[db][hs * 2], vh[db][hs * 2 + 1]);
                }
            }
        }
    }

    const float inv0 = 1.f / l0, inv1 = 1.f / l1;
    const int bb = hg >> 4, hh = hg & 15;
    const int q0 = qt * 64 + w * 16 + rg;
    #pragma unroll
    for (int nt = 0; nt < 8; nt++) {
        const int d = hh * 64 + nt * 8 + tig * 2;
        *(float2*)(ctx + ((size_t)q0 * B_DIM + bb) * E_DIM + d) =
            make_float2(to_tf32(o[nt][0] * inv0), to_tf32(o[nt][1] * inv0));
        *(float2*)(ctx + ((size_t)(q0 + 8) * B_DIM + bb) * E_DIM + d) =
            make_float2(to_tf32(o[nt][2] * inv1), to_tf32(o[nt][3] * inv1));
    }
}

// ---------------------------------------------------------------------------
extern "C" void kernel_launch(void* const* d_in, const int* in_sizes, int n_in,
                              void* d_out, int out_size)
{
    const float* query = (const float*)d_in[0];
    const float* key   = (const float*)d_in[1];
    const float* value = (const float*)d_in[2];
    const float* Win   = (const float*)d_in[3];
    const float* bin   = (const float*)d_in[4];
    const float* Wout  = (const float*)d_in[5];
    const float* bout  = (const float*)d_in[6];
    float* out = (float*)d_out;

    float *Qtf, *Ktf, *ctx, *q_r, *k_r, *v_r, *Win_r, *Wout_r;
    __nv_bfloat16 *Vhb;
    cudaGetSymbolAddress((void**)&Qtf,    g_Qtf);
    cudaGetSymbolAddress((void**)&Ktf,    g_Ktf);
    cudaGetSymbolAddress((void**)&Vhb,    g_Vhb);
    cudaGetSymbolAddress((void**)&ctx,    g_ctx);
    cudaGetSymbolAddress((void**)&q_r,    g_q);
    cudaGetSymbolAddress((void**)&k_r,    g_k);
    cudaGetSymbolAddress((void**)&v_r,    g_v);
    cudaGetSymbolAddress((void**)&Win_r,  g_Win);
    cudaGetSymbolAddress((void**)&Wout_r, g_Wout);

    const float scaleQ = 0.125f * 1.44269504089f;   // 1/sqrt(64) * log2(e)

    cudaFuncSetAttribute(gemm_tf32, cudaFuncAttributeMaxDynamicSharedMemorySize, GSMEM);
    cudaFuncSetAttribute(attn_mma,  cudaFuncAttributeMaxDynamicSharedMemorySize, ATT_SMEM);

    preround_all<<<16384, 256>>>(query, key, value, Win, Wout);

    gemm_tf32<<<dim3(8, 32, 3), 512, GSMEM>>>(
        q_r, k_r, v_r, Win_r, bin, Qtf, Ktf, Vhb, nullptr, scaleQ, 1);

    attn_mma<<<dim3(32, 32), 128, ATT_SMEM>>>(Qtf, Ktf, Vhb, ctx);

    gemm_tf32<<<dim3(8, 32, 1), 512, GSMEM>>>(
        ctx, nullptr, nullptr, Wout_r, bout, nullptr, nullptr, nullptr, out, 1.f, 0);
}

// round 16
// speedup vs baseline: 1.2575x; 1.0777x over previous
#include <cuda_runtime.h>
#include <cuda_bf16.h>
#include <cuda_fp16.h>
#include <math_constants.h>
#include <cstdint>

#define T_DIM 2048
#define B_DIM 2
#define E_DIM 1024
#define H_DIM 16
#define D_DIM 64
#define NHEADS 32
#define NROWS  4096

// Scratch (device globals; no runtime allocation)
__device__ float  g_Qtf[NROWS * E_DIM];   // tf32, scale*log2e folded
__device__ float  g_Ktf[NROWS * E_DIM];   // tf32
__device__ __half g_Vh16[NROWS * E_DIM];  // fp16 V head tensor
__device__ float  g_ctx[NROWS * E_DIM];   // tf32-rounded
__device__ float  g_q[NROWS * E_DIM], g_k[NROWS * E_DIM], g_v[NROWS * E_DIM];
__device__ float  g_Win[3 * E_DIM * E_DIM], g_Wout[E_DIM * E_DIM];

// ---------------- helpers ----------------
__device__ __forceinline__ void ldsm4(uint32_t* r, uint32_t a) {
    asm volatile("ldmatrix.sync.aligned.m8n8.x4.shared.b16 {%0,%1,%2,%3}, [%4];"
                 : "=r"(r[0]), "=r"(r[1]), "=r"(r[2]), "=r"(r[3]) : "r"(a));
}
__device__ __forceinline__ void ldsm4t(uint32_t* r, uint32_t a) {
    asm volatile("ldmatrix.sync.aligned.m8n8.x4.trans.shared.b16 {%0,%1,%2,%3}, [%4];"
                 : "=r"(r[0]), "=r"(r[1]), "=r"(r[2]), "=r"(r[3]) : "r"(a));
}
__device__ __forceinline__ void mma_f16(float* d, const uint32_t* a, uint32_t b0, uint32_t b1) {
    asm volatile("mma.sync.aligned.m16n8k16.row.col.f32.f16.f16.f32 "
                 "{%0,%1,%2,%3}, {%4,%5,%6,%7}, {%8,%9}, {%0,%1,%2,%3};"
                 : "+f"(d[0]), "+f"(d[1]), "+f"(d[2]), "+f"(d[3])
                 : "r"(a[0]), "r"(a[1]), "r"(a[2]), "r"(a[3]), "r"(b0), "r"(b1));
}
__device__ __forceinline__ void mma_tf32(float* d, const uint32_t* a, uint32_t b0, uint32_t b1) {
    asm volatile("mma.sync.aligned.m16n8k8.row.col.f32.tf32.tf32.f32 "
                 "{%0,%1,%2,%3}, {%4,%5,%6,%7}, {%8,%9}, {%0,%1,%2,%3};"
                 : "+f"(d[0]), "+f"(d[1]), "+f"(d[2]), "+f"(d[3])
                 : "r"(a[0]), "r"(a[1]), "r"(a[2]), "r"(a[3]), "r"(b0), "r"(b1));
}
__device__ __forceinline__ uint32_t smem_u32(const void* p) {
    return (uint32_t)__cvta_generic_to_shared(p);
}
__device__ __forceinline__ void cp_async16(uint32_t d, const void* s) {
    asm volatile("cp.async.cg.shared.global [%0], [%1], 16;" :: "r"(d), "l"(s));
}
__device__ __forceinline__ void cp_commit() { asm volatile("cp.async.commit_group;"); }
template <int N> __device__ __forceinline__ void cp_wait() {
    asm volatile("cp.async.wait_group %0;" :: "n"(N));
}
__device__ __forceinline__ uint32_t pack_f16(float a, float b) {
    __half2 h = __floats2half2_rn(a, b);
    return *reinterpret_cast<uint32_t*>(&h);
}
__device__ __forceinline__ float to_tf32(float x) {
    uint32_t r; asm("cvt.rna.tf32.f32 %0, %1;" : "=r"(r) : "f"(x));
    return __uint_as_float(r);
}
__device__ __forceinline__ float ex2f(float x) {
    float y; asm("ex2.approx.ftz.f32 %0, %1;" : "=f"(y) : "f"(x));
    return y;
}

// ---------------- merged tf32-RNA preround (segment ladder, one launch) ----------------
__global__ __launch_bounds__(256) void preround_all(const float* __restrict__ q,
    const float* __restrict__ k, const float* __restrict__ v,
    const float* __restrict__ Win, const float* __restrict__ Wout)
{
    const long i = (long)blockIdx.x * 256 + threadIdx.x;
    const float* src; float* dst; long off;
    if (i < 1048576)      { src = q;    dst = g_q;    off = i; }
    else if (i < 2097152) { src = k;    dst = g_k;    off = i - 1048576; }
    else if (i < 3145728) { src = v;    dst = g_v;    off = i - 2097152; }
    else if (i < 3932160) { src = Win;  dst = g_Win;  off = i - 3145728; }
    else                  { src = Wout; dst = g_Wout; off = i - 3932160; }
    float4 x = ((const float4*)src)[off];
    ((float4*)dst)[off] = make_float4(to_tf32(x.x), to_tf32(x.y),
                                      to_tf32(x.z), to_tf32(x.w));
}

// ---------------- tf32 GEMM: 512 thr / 16 warps (4Mx4N), 2-stage cp.async ----------------
#define GT 18432
#define GSTAGE (2 * GT)
#define GSMEM (2 * GSTAGE)

__global__ __launch_bounds__(512, 2) void gemm_tf32(const float* __restrict__ A0,
    const float* __restrict__ A1, const float* __restrict__ A2,
    const float* __restrict__ W,  const float* __restrict__ bias,
    float* __restrict__ Qtf, float* __restrict__ Ktf,
    __half* __restrict__ Vh16,
    float* __restrict__ Cflat, float scaleQ, int qkv)
{
    extern __shared__ __align__(16) char gsm[];
    const int z = qkv ? blockIdx.z : 0;
    const float* A  = qkv ? (z == 0 ? A0 : (z == 1 ? A1 : A2)) : A0;
    const float* Wz = W + (size_t)z * E_DIM * E_DIM;
    const float* bz = bias + z * E_DIM;
    const int   mode  = qkv ? (z == 2 ? 1 : 2) : 0;
    const float scale = (qkv && z == 0) ? scaleQ : 1.f;
    float* Cf = (z == 0) ? Qtf : Ktf;

    const int tid = threadIdx.x, lane = tid & 31, wid = tid >> 5;
    const int wm = wid >> 2, wn = wid & 3;
    const int bm = blockIdx.y << 7, bn = blockIdx.x << 7;
    const int lrow = lane & 15, lk16 = ((lane >> 4) & 1) << 4;
    const uint32_t uS = smem_u32(gsm);

    float acc[2][4][4];
    #pragma unroll
    for (int i = 0; i < 2; i++)
        #pragma unroll
        for (int j = 0; j < 4; j++)
            #pragma unroll
            for (int r = 0; r < 4; r++) acc[i][j][r] = 0.f;

    const float* gA = A  + (size_t)bm * E_DIM;
    const float* gW = Wz + (size_t)bn * E_DIM;

    #pragma unroll
    for (int s = 0; s < 2; s++) {
        const uint32_t dst = uS + (uint32_t)s * GSTAGE;
        const int kc = s * 32;
        #pragma unroll
        for (int it = 0; it < 2; it++) {
            const int idx = tid + it * 512;
            const int row = idx >> 3, j = idx & 7;
            const uint32_t off = (uint32_t)row * 144 + (uint32_t)(j * 16);
            cp_async16(dst + off,      gA + (size_t)row * E_DIM + kc + j * 4);
            cp_async16(dst + GT + off, gW + (size_t)row * E_DIM + kc + j * 4);
        }
        cp_commit();
    }

    const int NK = E_DIM / 32;
    for (int kt = 0; kt < NK; kt++) {
        cp_wait<1>();
        __syncthreads();

        const uint32_t pA = uS + (uint32_t)(kt & 1) * GSTAGE;
        const uint32_t pW = pA + GT;
        #pragma unroll
        for (int kk = 0; kk < 4; kk++) {
            uint32_t Af[2][4];
            #pragma unroll
            for (int mt = 0; mt < 2; mt++)
                ldsm4(Af[mt], pA + (uint32_t)(wm * 32 + mt * 16 + lrow) * 144 + kk * 32 + lk16);
            uint32_t Bf[2][4];
            #pragma unroll
            for (int nb = 0; nb < 2; nb++)
                ldsm4(Bf[nb], pW + (uint32_t)(wn * 32 + nb * 16 + lrow) * 144 + kk * 32 + lk16);
            #pragma unroll
            for (int mt = 0; mt < 2; mt++) {
                #pragma unroll
                for (int nt = 0; nt < 4; nt++) {
                    const int nb = nt >> 1, hf = nt & 1;
                    mma_tf32(acc[mt][nt], Af[mt], Bf[nb][hf], Bf[nb][hf + 2]);
                }
            }
        }

        __syncthreads();
        if (kt + 2 < NK) {
            const uint32_t dst = uS + (uint32_t)(kt & 1) * GSTAGE;
            const int kc = (kt + 2) * 32;
            #pragma unroll
            for (int it = 0; it < 2; it++) {
                const int idx = tid + it * 512;
                const int row = idx >> 3, j = idx & 7;
                const uint32_t off = (uint32_t)row * 144 + (uint32_t)(j * 16);
                cp_async16(dst + off,      gA + (size_t)row * E_DIM + kc + j * 4);
                cp_async16(dst + GT + off, gW + (size_t)row * E_DIM + kc + j * 4);
            }
        }
        cp_commit();
    }

    // ---- epilogue ----
    const int g = lane >> 2, tig = lane & 3;
    #pragma unroll
    for (int mt = 0; mt < 2; mt++) {
        #pragma unroll
        for (int nt = 0; nt < 4; nt++) {
            const int m0 = bm + wm * 32 + mt * 16 + g;
            const int n0 = bn + wn * 32 + nt * 8 + tig * 2;
            const float b0 = bz[n0], b1 = bz[n0 + 1];
            float v[4];
            #pragma unroll
            for (int r = 0; r < 4; r++)
                v[r] = (acc[mt][nt][r] + ((r & 1) ? b1 : b0)) * scale;
            if (mode == 1) {
                #pragma unroll
                for (int rr = 0; rr < 2; rr++) {
                    const int m = m0 + rr * 8;
                    const int t = m >> 1, b = m & 1, h = n0 >> 6, dd = n0 & 63;
                    const size_t idx = (((size_t)(b * H_DIM + h)) * T_DIM + t) * D_DIM + dd;
                    *reinterpret_cast<uint32_t*>(&Vh16[idx]) = pack_f16(v[rr * 2], v[rr * 2 + 1]);
                }
            } else if (mode == 2) {
                #pragma unroll
                for (int rr = 0; rr < 2; rr++) {
                    const int m = m0 + rr * 8;
                    const int t = m >> 1, b = m & 1, h = n0 >> 6, dd = n0 & 63;
                    const size_t idx = (((size_t)(b * H_DIM + h)) * T_DIM + t) * D_DIM + dd;
                    *(float2*)(Cf + idx) = make_float2(to_tf32(v[rr * 2]),
                                                       to_tf32(v[rr * 2 + 1]));
                }
            } else {
                #pragma unroll
                for (int r = 0; r < 4; r++) {
                    const int m = m0 + ((r >> 1) << 3);
                    const int n = n0 + (r & 1);
                    Cflat[(size_t)m * E_DIM + n] = v[r];
                }
            }
        }
    }
}

// ---------------- flash attention: 64q, occ 4, single-pass fp16 PV ----------------
#define AOFF_Q  0
#define AOFF_K  17408
#define AOFF_VH 34816
#define ATT_SMEM 44032

__global__ __launch_bounds__(128, 4) void attn_mma(
    const float* __restrict__ Qtf, const float* __restrict__ Ktf,
    const __half* __restrict__ Vh16,
    float* __restrict__ ctx)
{
    extern __shared__ __align__(16) char smraw[];
    const int tid = threadIdx.x, lane = tid & 31, w = tid >> 5;
    const int qt = blockIdx.x, hg = blockIdx.y;
    const int lrow = lane & 15, lk16 = ((lane >> 4) & 1) << 4;
    const int rg = lane >> 2, tig = lane & 3;
    const uint32_t uSM = smem_u32(smraw);

    {
        const float* gq = Qtf + ((size_t)hg * T_DIM + qt * 64) * D_DIM;
        #pragma unroll
        for (int i = 0; i < 8; i++) {
            int c = tid + i * 128, row = c >> 4, j = c & 15;
            cp_async16(uSM + AOFF_Q + row * 272 + j * 16, gq + c * 4);
        }
        cp_commit();
    }

    float o[8][4];
    #pragma unroll
    for (int nt = 0; nt < 8; nt++)
        #pragma unroll
        for (int r = 0; r < 4; r++) o[nt][r] = 0.f;
    float m0 = -CUDART_INF_F, m1 = -CUDART_INF_F, l0 = 0.f, l1 = 0.f;

    const float* gK = Ktf + (size_t)hg * T_DIM * D_DIM;
    const __half* gVh = Vh16 + (size_t)hg * T_DIM * D_DIM;

    for (int st = 0; st < T_DIM / 64; st++) {
        __syncthreads();
        #pragma unroll
        for (int i = 0; i < 8; i++) {
            int c = tid + i * 128, row = c >> 4, j = c & 15;
            cp_async16(uSM + AOFF_K + row * 272 + j * 16, gK + (size_t)st * 4096 + c * 4);
        }
        cp_commit();
        #pragma unroll
        for (int i = 0; i < 4; i++) {
            int c = tid + i * 128, row = c >> 3, j = c & 7;
            cp_async16(uSM + AOFF_VH + row * 144 + j * 16, gVh + (size_t)st * 4096 + c * 8);
        }
        cp_commit();
        cp_wait<1>();      // K(st) (+Q at st=0) resident; V in flight
        __syncthreads();

        float s[8][4];
        #pragma unroll
        for (int nt = 0; nt < 8; nt++)
            #pragma unroll
            for (int r = 0; r < 4; r++) s[nt][r] = 0.f;
        #pragma unroll
        for (int kk = 0; kk < 8; kk++) {
            uint32_t qa[4];
            ldsm4(qa, uSM + AOFF_Q + (uint32_t)(w * 16 + lrow) * 272 + kk * 32 + lk16);
            uint32_t kf[4][4];
            #pragma unroll
            for (int nb = 0; nb < 4; nb++)
                ldsm4(kf[nb], uSM + AOFF_K + (uint32_t)(nb * 16 + lrow) * 272 + kk * 32 + lk16);
            #pragma unroll
            for (int nb = 0; nb < 4; nb++) {
                mma_tf32(s[2 * nb],     qa, kf[nb][0], kf[nb][2]);
                mma_tf32(s[2 * nb + 1], qa, kf[nb][1], kf[nb][3]);
            }
        }

        float mx0 = -CUDART_INF_F, mx1 = -CUDART_INF_F;
        #pragma unroll
        for (int nt = 0; nt < 8; nt++) {
            mx0 = fmaxf(mx0, fmaxf(s[nt][0], s[nt][1]));
            mx1 = fmaxf(mx1, fmaxf(s[nt][2], s[nt][3]));
        }
        mx0 = fmaxf(mx0, __shfl_xor_sync(~0u, mx0, 1));
        mx0 = fmaxf(mx0, __shfl_xor_sync(~0u, mx0, 2));
        mx1 = fmaxf(mx1, __shfl_xor_sync(~0u, mx1, 1));
        mx1 = fmaxf(mx1, __shfl_xor_sync(~0u, mx1, 2));
        const float mn0 = fmaxf(m0, mx0), mn1 = fmaxf(m1, mx1);
        const float al0 = ex2f(m0 - mn0), al1 = ex2f(m1 - mn1);
        m0 = mn0; m1 = mn1;
        float sum0 = 0.f, sum1 = 0.f;
        #pragma unroll
        for (int nt = 0; nt < 8; nt++) {
            s[nt][0] = ex2f(s[nt][0] - m0); s[nt][1] = ex2f(s[nt][1] - m0);
            s[nt][2] = ex2f(s[nt][2] - m1); s[nt][3] = ex2f(s[nt][3] - m1);
            sum0 += s[nt][0] + s[nt][1];
            sum1 += s[nt][2] + s[nt][3];
        }
        sum0 += __shfl_xor_sync(~0u, sum0, 1); sum0 += __shfl_xor_sync(~0u, sum0, 2);
        sum1 += __shfl_xor_sync(~0u, sum1, 1); sum1 += __shfl_xor_sync(~0u, sum1, 2);
        l0 = l0 * al0 + sum0; l1 = l1 * al1 + sum1;
        #pragma unroll
        for (int nt = 0; nt < 8; nt++) {
            o[nt][0] *= al0; o[nt][1] *= al0; o[nt][2] *= al1; o[nt][3] *= al1;
        }

        // ---- P -> fp16 A fragments (single pass) ----
        uint32_t AH[4][4];
        #pragma unroll
        for (int kb = 0; kb < 4; kb++) {
            const int t0 = 2 * kb, t1 = 2 * kb + 1;
            AH[kb][0] = pack_f16(s[t0][0], s[t0][1]);
            AH[kb][1] = pack_f16(s[t0][2], s[t0][3]);
            AH[kb][2] = pack_f16(s[t1][0], s[t1][1]);
            AH[kb][3] = pack_f16(s[t1][2], s[t1][3]);
        }

        cp_wait<0>();      // V(st) resident
        __syncthreads();
        #pragma unroll
        for (int kb = 0; kb < 4; kb++) {
            uint32_t vh[4][4];
            #pragma unroll
            for (int db = 0; db < 4; db++)
                ldsm4t(vh[db], uSM + AOFF_VH + (uint32_t)(kb * 16 + lrow) * 144 + db * 32 + lk16);
            #pragma unroll
            for (int db = 0; db < 4; db++) {
                #pragma unroll
                for (int hs = 0; hs < 2; hs++) {
                    const int nt = db * 2 + hs;
                    mma_f16(o[nt], AH[kb], vh[db][hs * 2], vh[db][hs * 2 + 1]);
                }
            }
        }
    }

    const float inv0 = 1.f / l0, inv1 = 1.f / l1;
    const int bb = hg >> 4, hh = hg & 15;
    const int q0 = qt * 64 + w * 16 + rg;
    #pragma unroll
    for (int nt = 0; nt < 8; nt++) {
        const int d = hh * 64 + nt * 8 + tig * 2;
        *(float2*)(ctx + ((size_t)q0 * B_DIM + bb) * E_DIM + d) =
            make_float2(to_tf32(o[nt][0] * inv0), to_tf32(o[nt][1] * inv0));
        *(float2*)(ctx + ((size_t)(q0 + 8) * B_DIM + bb) * E_DIM + d) =
            make_float2(to_tf32(o[nt][2] * inv1), to_tf32(o[nt][3] * inv1));
    }
}

// ---------------------------------------------------------------------------
extern "C" void kernel_launch(void* const* d_in, const int* in_sizes, int n_in,
                              void* d_out, int out_size)
{
    const float* query = (const float*)d_in[0];
    const float* key   = (const float*)d_in[1];
    const float* value = (const float*)d_in[2];
    const float* Win   = (const float*)d_in[3];
    const float* bin   = (const float*)d_in[4];
    const float* Wout  = (const float*)d_in[5];
    const float* bout  = (const float*)d_in[6];
    float* out = (float*)d_out;

    float *Qtf, *Ktf, *ctx, *q_r, *k_r, *v_r, *Win_r, *Wout_r;
    __half *Vh16;
    cudaGetSymbolAddress((void**)&Qtf,    g_Qtf);
    cudaGetSymbolAddress((void**)&Ktf,    g_Ktf);
    cudaGetSymbolAddress((void**)&Vh16,   g_Vh16);
    cudaGetSymbolAddress((void**)&ctx,    g_ctx);
    cudaGetSymbolAddress((void**)&q_r,    g_q);
    cudaGetSymbolAddress((void**)&k_r,    g_k);
    cudaGetSymbolAddress((void**)&v_r,    g_v);
    cudaGetSymbolAddress((void**)&Win_r,  g_Win);
    cudaGetSymbolAddress((void**)&Wout_r, g_Wout);

    const float scaleQ = 0.125f * 1.44269504089f;   // 1/sqrt(64) * log2(e)

    cudaFuncSetAttribute(gemm_tf32, cudaFuncAttributeMaxDynamicSharedMemorySize, GSMEM);
    cudaFuncSetAttribute(attn_mma,  cudaFuncAttributeMaxDynamicSharedMemorySize, ATT_SMEM);

    preround_all<<<16384, 256>>>(query, key, value, Win, Wout);

    gemm_tf32<<<dim3(8, 32, 3), 512, GSMEM>>>(
        q_r, k_r, v_r, Win_r, bin, Qtf, Ktf, Vh16, nullptr, scaleQ, 1);

    attn_mma<<<dim3(32, 32), 128, ATT_SMEM>>>(Qtf, Ktf, Vh16, ctx);

    gemm_tf32<<<dim3(8, 32, 1), 512, GSMEM>>>(
        ctx, nullptr, nullptr, Wout_r, bout, nullptr, nullptr, nullptr, out, 1.f, 0);
}

// round 17
// speedup vs baseline: 1.9552x; 1.5548x over previous
#include <cuda_runtime.h>
#include <cuda_fp16.h>
#include <math_constants.h>
#include <cstdint>

#define T_DIM 2048
#define B_DIM 2
#define E_DIM 1024
#define H_DIM 16
#define D_DIM 64
#define NHEADS 32
#define NROWS  4096

// Scratch (device globals; no runtime allocation)
__device__ __half g_Qf[NROWS * E_DIM];    // fp16, scale*log2e folded
__device__ __half g_Kf[NROWS * E_DIM];    // fp16
__device__ __half g_Vf[NROWS * E_DIM];    // fp16
__device__ __half g_ctx[NROWS * E_DIM];   // fp16
__device__ __half g_q[NROWS * E_DIM], g_k[NROWS * E_DIM], g_v[NROWS * E_DIM];
__device__ __half g_Win[3 * E_DIM * E_DIM], g_Wout[E_DIM * E_DIM];

// ---------------- helpers ----------------
__device__ __forceinline__ void ldsm4(uint32_t* r, uint32_t a) {
    asm volatile("ldmatrix.sync.aligned.m8n8.x4.shared.b16 {%0,%1,%2,%3}, [%4];"
                 : "=r"(r[0]), "=r"(r[1]), "=r"(r[2]), "=r"(r[3]) : "r"(a));
}
__device__ __forceinline__ void ldsm4t(uint32_t* r, uint32_t a) {
    asm volatile("ldmatrix.sync.aligned.m8n8.x4.trans.shared.b16 {%0,%1,%2,%3}, [%4];"
                 : "=r"(r[0]), "=r"(r[1]), "=r"(r[2]), "=r"(r[3]) : "r"(a));
}
__device__ __forceinline__ void mma_f16(float* d, const uint32_t* a, uint32_t b0, uint32_t b1) {
    asm volatile("mma.sync.aligned.m16n8k16.row.col.f32.f16.f16.f32 "
                 "{%0,%1,%2,%3}, {%4,%5,%6,%7}, {%8,%9}, {%0,%1,%2,%3};"
                 : "+f"(d[0]), "+f"(d[1]), "+f"(d[2]), "+f"(d[3])
                 : "r"(a[0]), "r"(a[1]), "r"(a[2]), "r"(a[3]), "r"(b0), "r"(b1));
}
__device__ __forceinline__ uint32_t smem_u32(const void* p) {
    return (uint32_t)__cvta_generic_to_shared(p);
}
__device__ __forceinline__ void cp_async16(uint32_t d, const void* s) {
    asm volatile("cp.async.cg.shared.global [%0], [%1], 16;" :: "r"(d), "l"(s));
}
__device__ __forceinline__ void cp_commit() { asm volatile("cp.async.commit_group;"); }
template <int N> __device__ __forceinline__ void cp_wait() {
    asm volatile("cp.async.wait_group %0;" :: "n"(N));
}
__device__ __forceinline__ uint32_t pack_f16(float a, float b) {
    __half2 h = __floats2half2_rn(a, b);
    return *reinterpret_cast<uint32_t*>(&h);
}
__device__ __forceinline__ float ex2f(float x) {
    float y; asm("ex2.approx.ftz.f32 %0, %1;" : "=f"(y) : "f"(x));
    return y;
}

// ---------------- fp32 -> fp16 conversion of all GEMM operands (one launch) ----------------
__global__ __launch_bounds__(256) void preconv_all(const float* __restrict__ q,
    const float* __restrict__ k, const float* __restrict__ v,
    const float* __restrict__ Win, const float* __restrict__ Wout)
{
    const long i = (long)blockIdx.x * 256 + threadIdx.x;
    const float* src; __half* dst; long off;
    if (i < 1048576)      { src = q;    dst = g_q;    off = i; }
    else if (i < 2097152) { src = k;    dst = g_k;    off = i - 1048576; }
    else if (i < 3145728) { src = v;    dst = g_v;    off = i - 2097152; }
    else if (i < 3932160) { src = Win;  dst = g_Win;  off = i - 3145728; }
    else                  { src = Wout; dst = g_Wout; off = i - 3932160; }
    float4 x = ((const float4*)src)[off];
    ((uint2*)dst)[off] = make_uint2(pack_f16(x.x, x.y), pack_f16(x.z, x.w));
}

// ---------------- fp16 GEMM: 128x128 tile, K-tile 32, 512 thr / 16 warps, 2-stage ----------------
#define GT 10240                   // one tensor tile: 128 rows * 80B
#define GSTAGE (2 * GT)            // A + W
#define GSMEM (2 * GSTAGE)         // 40960

__global__ __launch_bounds__(512, 2) void gemm_f16(const __half* __restrict__ A0,
    const __half* __restrict__ A1, const __half* __restrict__ A2,
    const __half* __restrict__ W,  const float* __restrict__ bias,
    __half* __restrict__ Qf, __half* __restrict__ Kf, __half* __restrict__ Vf,
    float* __restrict__ Cflat, float scaleQ, int qkv)
{
    extern __shared__ __align__(16) char gsm[];
    const int z = qkv ? blockIdx.z : 0;
    const __half* A  = qkv ? (z == 0 ? A0 : (z == 1 ? A1 : A2)) : A0;
    const __half* Wz = W + (size_t)z * E_DIM * E_DIM;
    const float* bz = bias + z * E_DIM;
    const int   mode  = qkv ? (z == 2 ? 1 : 2) : 0;
    const float scale = (qkv && z == 0) ? scaleQ : 1.f;
    __half* Cf = (z == 0) ? Qf : Kf;

    const int tid = threadIdx.x, lane = tid & 31, wid = tid >> 5;
    const int wm = wid >> 2, wn = wid & 3;
    const int bm = blockIdx.y << 7, bn = blockIdx.x << 7;
    const int lrow = lane & 15, lk16 = ((lane >> 4) & 1) << 4;
    const uint32_t uS = smem_u32(gsm);

    float acc[2][4][4];
    #pragma unroll
    for (int i = 0; i < 2; i++)
        #pragma unroll
        for (int j = 0; j < 4; j++)
            #pragma unroll
            for (int r = 0; r < 4; r++) acc[i][j][r] = 0.f;

    // copy mapping: tile = 128 rows x 32 fp16 = 512 16B-chunks, 1 per thread per tensor
    const int crow = tid >> 2, cj = tid & 3;
    const __half* gA = A  + (size_t)bm * E_DIM;
    const __half* gW = Wz + (size_t)bn * E_DIM;

    #pragma unroll
    for (int s = 0; s < 2; s++) {
        const uint32_t dst = uS + (uint32_t)s * GSTAGE;
        const int kc = s * 32;
        const uint32_t off = (uint32_t)crow * 80 + (uint32_t)(cj * 16);
        cp_async16(dst + off,      gA + (size_t)crow * E_DIM + kc + cj * 8);
        cp_async16(dst + GT + off, gW + (size_t)crow * E_DIM + kc + cj * 8);
        cp_commit();
    }

    const int NK = E_DIM / 32;   // 32
    for (int kt = 0; kt < NK; kt++) {
        cp_wait<1>();
        __syncthreads();

        const uint32_t pA = uS + (uint32_t)(kt & 1) * GSTAGE;
        const uint32_t pW = pA + GT;
        #pragma unroll
        for (int kk = 0; kk < 2; kk++) {
            const int kbyte = kk * 32 + lk16;
            uint32_t Af[2][4];
            #pragma unroll
            for (int mt = 0; mt < 2; mt++)
                ldsm4(Af[mt], pA + (uint32_t)(wm * 32 + mt * 16 + lrow) * 80 + kbyte);
            uint32_t Bf[2][4];
            #pragma unroll
            for (int nb = 0; nb < 2; nb++)
                ldsm4(Bf[nb], pW + (uint32_t)(wn * 32 + nb * 16 + lrow) * 80 + kbyte);
            #pragma unroll
            for (int mt = 0; mt < 2; mt++) {
                #pragma unroll
                for (int nt = 0; nt < 4; nt++) {
                    const int nb = nt >> 1, hf = nt & 1;
                    mma_f16(acc[mt][nt], Af[mt], Bf[nb][hf], Bf[nb][hf + 2]);
                }
            }
        }

        __syncthreads();
        if (kt + 2 < NK) {
            const uint32_t dst = uS + (uint32_t)(kt & 1) * GSTAGE;
            const int kc = (kt + 2) * 32;
            const uint32_t off = (uint32_t)crow * 80 + (uint32_t)(cj * 16);
            cp_async16(dst + off,      gA + (size_t)crow * E_DIM + kc + cj * 8);
            cp_async16(dst + GT + off, gW + (size_t)crow * E_DIM + kc + cj * 8);
        }
        cp_commit();
    }

    // ---- epilogue ----
    const int g = lane >> 2, tig = lane & 3;
    #pragma unroll
    for (int mt = 0; mt < 2; mt++) {
        #pragma unroll
        for (int nt = 0; nt < 4; nt++) {
            const int m0 = bm + wm * 32 + mt * 16 + g;
            const int n0 = bn + wn * 32 + nt * 8 + tig * 2;
            const float b0 = bz[n0], b1 = bz[n0 + 1];
            float v[4];
            #pragma unroll
            for (int r = 0; r < 4; r++)
                v[r] = (acc[mt][nt][r] + ((r & 1) ? b1 : b0)) * scale;
            if (mode == 0) {
                #pragma unroll
                for (int r = 0; r < 4; r++) {
                    const int m = m0 + ((r >> 1) << 3);
                    const int n = n0 + (r & 1);
                    Cflat[(size_t)m * E_DIM + n] = v[r];
                }
            } else {
                __half* dst = (mode == 1) ? Vf : Cf;
                #pragma unroll
                for (int rr = 0; rr < 2; rr++) {
                    const int m = m0 + rr * 8;
                    const int t = m >> 1, b = m & 1, h = n0 >> 6, dd = n0 & 63;
                    const size_t idx = (((size_t)(b * H_DIM + h)) * T_DIM + t) * D_DIM + dd;
                    *reinterpret_cast<uint32_t*>(&dst[idx]) = pack_f16(v[rr * 2], v[rr * 2 + 1]);
                }
            }
        }
    }
}

// ---------------- flash attention: 64q, occ 4, fp16 QK + fp16 PV ----------------
#define AOFF_Q  0
#define AOFF_K  9216
#define AOFF_V  18432
#define ATT_SMEM 27648

__global__ __launch_bounds__(128, 4) void attn_mma(
    const __half* __restrict__ Qf, const __half* __restrict__ Kf,
    const __half* __restrict__ Vf,
    __half* __restrict__ ctx)
{
    extern __shared__ __align__(16) char smraw[];
    const int tid = threadIdx.x, lane = tid & 31, w = tid >> 5;
    const int qt = blockIdx.x, hg = blockIdx.y;
    const int lrow = lane & 15, lk16 = ((lane >> 4) & 1) << 4;
    const int rg = lane >> 2, tig = lane & 3;
    const uint32_t uSM = smem_u32(smraw);

    // prologue: Q tile (64 rows x 64 fp16 = 512 chunks), group
    {
        const __half* gq = Qf + ((size_t)hg * T_DIM + qt * 64) * D_DIM;
        #pragma unroll
        for (int i = 0; i < 4; i++) {
            int c = tid + i * 128, row = c >> 3, j = c & 7;
            cp_async16(uSM + AOFF_Q + row * 144 + j * 16, gq + c * 8);
        }
        cp_commit();
    }

    float o[8][4];
    #pragma unroll
    for (int nt = 0; nt < 8; nt++)
        #pragma unroll
        for (int r = 0; r < 4; r++) o[nt][r] = 0.f;
    float m0 = -CUDART_INF_F, m1 = -CUDART_INF_F, l0 = 0.f, l1 = 0.f;

    const __half* gK = Kf + (size_t)hg * T_DIM * D_DIM;
    const __half* gV = Vf + (size_t)hg * T_DIM * D_DIM;

    for (int st = 0; st < T_DIM / 64; st++) {
        __syncthreads();
        #pragma unroll
        for (int i = 0; i < 4; i++) {
            int c = tid + i * 128, row = c >> 3, j = c & 7;
            cp_async16(uSM + AOFF_K + row * 144 + j * 16, gK + (size_t)st * 4096 + c * 8);
        }
        cp_commit();
        #pragma unroll
        for (int i = 0; i < 4; i++) {
            int c = tid + i * 128, row = c >> 3, j = c & 7;
            cp_async16(uSM + AOFF_V + row * 144 + j * 16, gV + (size_t)st * 4096 + c * 8);
        }
        cp_commit();
        cp_wait<1>();      // K(st) (+Q at st=0) resident; V in flight
        __syncthreads();

        // ---- S = Q K^T (fp16 single pass) ----
        float s[8][4];
        #pragma unroll
        for (int nt = 0; nt < 8; nt++)
            #pragma unroll
            for (int r = 0; r < 4; r++) s[nt][r] = 0.f;
        #pragma unroll
        for (int kb = 0; kb < 4; kb++) {
            uint32_t qa[4];
            ldsm4(qa, uSM + AOFF_Q + (uint32_t)(w * 16 + lrow) * 144 + kb * 32 + lk16);
            uint32_t kf[4][4];
            #pragma unroll
            for (int nb = 0; nb < 4; nb++)
                ldsm4(kf[nb], uSM + AOFF_K + (uint32_t)(nb * 16 + lrow) * 144 + kb * 32 + lk16);
            #pragma unroll
            for (int nb = 0; nb < 4; nb++) {
                mma_f16(s[2 * nb],     qa, kf[nb][0], kf[nb][2]);
                mma_f16(s[2 * nb + 1], qa, kf[nb][1], kf[nb][3]);
            }
        }

        // ---- online softmax (exp2 domain) ----
        float mx0 = -CUDART_INF_F, mx1 = -CUDART_INF_F;
        #pragma unroll
        for (int nt = 0; nt < 8; nt++) {
            mx0 = fmaxf(mx0, fmaxf(s[nt][0], s[nt][1]));
            mx1 = fmaxf(mx1, fmaxf(s[nt][2], s[nt][3]));
        }
        mx0 = fmaxf(mx0, __shfl_xor_sync(~0u, mx0, 1));
        mx0 = fmaxf(mx0, __shfl_xor_sync(~0u, mx0, 2));
        mx1 = fmaxf(mx1, __shfl_xor_sync(~0u, mx1, 1));
        mx1 = fmaxf(mx1, __shfl_xor_sync(~0u, mx1, 2));
        const float mn0 = fmaxf(m0, mx0), mn1 = fmaxf(m1, mx1);
        const float al0 = ex2f(m0 - mn0), al1 = ex2f(m1 - mn1);
        m0 = mn0; m1 = mn1;
        float sum0 = 0.f, sum1 = 0.f;
        #pragma unroll
        for (int nt = 0; nt < 8; nt++) {
            s[nt][0] = ex2f(s[nt][0] - m0); s[nt][1] = ex2f(s[nt][1] - m0);
            s[nt][2] = ex2f(s[nt][2] - m1); s[nt][3] = ex2f(s[nt][3] - m1);
            sum0 += s[nt][0] + s[nt][1];
            sum1 += s[nt][2] + s[nt][3];
        }
        sum0 += __shfl_xor_sync(~0u, sum0, 1); sum0 += __shfl_xor_sync(~0u, sum0, 2);
        sum1 += __shfl_xor_sync(~0u, sum1, 1); sum1 += __shfl_xor_sync(~0u, sum1, 2);
        l0 = l0 * al0 + sum0; l1 = l1 * al1 + sum1;
        #pragma unroll
        for (int nt = 0; nt < 8; nt++) {
            o[nt][0] *= al0; o[nt][1] *= al0; o[nt][2] *= al1; o[nt][3] *= al1;
        }

        // ---- P -> fp16 A fragments ----
        uint32_t AH[4][4];
        #pragma unroll
        for (int kb = 0; kb < 4; kb++) {
            const int t0 = 2 * kb, t1 = 2 * kb + 1;
            AH[kb][0] = pack_f16(s[t0][0], s[t0][1]);
            AH[kb][1] = pack_f16(s[t0][2], s[t0][3]);
            AH[kb][2] = pack_f16(s[t1][0], s[t1][1]);
            AH[kb][3] = pack_f16(s[t1][2], s[t1][3]);
        }

        cp_wait<0>();      // V(st) resident
        __syncthreads();
        #pragma unroll
        for (int kb = 0; kb < 4; kb++) {
            uint32_t vh[4][4];
            #pragma unroll
            for (int db = 0; db < 4; db++)
                ldsm4t(vh[db], uSM + AOFF_V + (uint32_t)(kb * 16 + lrow) * 144 + db * 32 + lk16);
            #pragma unroll
            for (int db = 0; db < 4; db++) {
                #pragma unroll
                for (int hs = 0; hs < 2; hs++) {
                    const int nt = db * 2 + hs;
                    mma_f16(o[nt], AH[kb], vh[db][hs * 2], vh[db][hs * 2 + 1]);
                }
            }
        }
    }

    // ---- epilogue: fp16 ctx (feeds fp16 out-projection) ----
    const float inv0 = 1.f / l0, inv1 = 1.f / l1;
    const int bb = hg >> 4, hh = hg & 15;
    const int q0 = qt * 64 + w * 16 + rg;
    #pragma unroll
    for (int nt = 0; nt < 8; nt++) {
        const int d = hh * 64 + nt * 8 + tig * 2;
        size_t idx = ((size_t)q0 * B_DIM + bb) * E_DIM + d;
        *reinterpret_cast<uint32_t*>(&ctx[idx]) = pack_f16(o[nt][0] * inv0, o[nt][1] * inv0);
        idx = ((size_t)(q0 + 8) * B_DIM + bb) * E_DIM + d;
        *reinterpret_cast<uint32_t*>(&ctx[idx]) = pack_f16(o[nt][2] * inv1, o[nt][3] * inv1);
    }
}

// ---------------------------------------------------------------------------
extern "C" void kernel_launch(void* const* d_in, const int* in_sizes, int n_in,
                              void* d_out, int out_size)
{
    const float* query = (const float*)d_in[0];
    const float* key   = (const float*)d_in[1];
    const float* value = (const float*)d_in[2];
    const float* Win   = (const float*)d_in[3];
    const float* bin   = (const float*)d_in[4];
    const float* Wout  = (const float*)d_in[5];
    const float* bout  = (const float*)d_in[6];
    float* out = (float*)d_out;

    __half *Qf, *Kf, *Vf, *ctx, *q_h, *k_h, *v_h, *Win_h, *Wout_h;
    cudaGetSymbolAddress((void**)&Qf,     g_Qf);
    cudaGetSymbolAddress((void**)&Kf,     g_Kf);
    cudaGetSymbolAddress((void**)&Vf,     g_Vf);
    cudaGetSymbolAddress((void**)&ctx,    g_ctx);
    cudaGetSymbolAddress((void**)&q_h,    g_q);
    cudaGetSymbolAddress((void**)&k_h,    g_k);
    cudaGetSymbolAddress((void**)&v_h,    g_v);
    cudaGetSymbolAddress((void**)&Win_h,  g_Win);
    cudaGetSymbolAddress((void**)&Wout_h, g_Wout);

    const float scaleQ = 0.125f * 1.44269504089f;   // 1/sqrt(64) * log2(e)

    cudaFuncSetAttribute(gemm_f16, cudaFuncAttributeMaxDynamicSharedMemorySize, GSMEM);
    cudaFuncSetAttribute(attn_mma, cudaFuncAttributeMaxDynamicSharedMemorySize, ATT_SMEM);

    preconv_all<<<16384, 256>>>(query, key, value, Win, Wout);

    gemm_f16<<<dim3(8, 32, 3), 512, GSMEM>>>(
        q_h, k_h, v_h, Win_h, bin, Qf, Kf, Vf, nullptr, scaleQ, 1);

    attn_mma<<<dim3(32, 32), 128, ATT_SMEM>>>(Qf, Kf, Vf, ctx);

    gemm_f16<<<dim3(8, 32, 1), 512, GSMEM>>>(
        ctx, nullptr, nullptr, Wout_h, bout, nullptr, nullptr, nullptr, out, 1.f, 0);
}